// round 12
// baseline (speedup 1.0000x reference)
#include <cuda_runtime.h>
#include <cuda_fp16.h>
#include <cstdint>

#define BB 2
#define FF 48
#define CC 96
#define HH 320
#define WW 320
#define HWW (HH*WW)

#define STRIP 256
#define NSTRIP (HWW/STRIP)   // 400
#define NJOBS (NSTRIP*BB)    // 800
#define CHUNK 16
#define NCH (CC/CHUNK)       // 6
#define NCTAS 148
#define AROWS (3*258)        // 774 halo rows of 32B

// smem: B weights (k-permuted rows) | 2 A buffers (XOR-swizzled); s_sig aliases A
#define SB_BYTES (NCH*9*CC*32)             // 165888
#define ABUF_BYTES 24832                   // 774*32=24768 padded to 256B
#define SA_OFF SB_BYTES
#define SMEM_BYTES (SB_BYTES + 2*ABUF_BYTES)  // 215552
#define SSIG_BYTES (STRIP*CC*2)            // 49152 <= 2*ABUF_BYTES

// sigma'd activations, fp16, pixel-interleaved by 16-ch chunk: [b][ci][pix][k16]
__device__ __align__(16) __half g_sig0[(size_t)BB*NCH*HWW*CHUNK];
__device__ __align__(16) __half g_sig1[(size_t)BB*NCH*HWW*CHUNK];
// weights: fp16, [ci][tap][cout96][k16], k-permuted per row
__device__ float  g_w0[2*9*CC];
__device__ __align__(16) __half g_w1[NCH*9*CC*CHUNK];
__device__ __align__(16) __half g_w2[NCH*9*CC*CHUNK];
__device__ float g_b0[CC];
__device__ float g_b1[CC];
__device__ float g_b2[CC];

__device__ __forceinline__ float sigma_f(float u) {
    float quad = fmaf(u, fmaf(u, 250.0f, 0.5f), 0.00025f);
    return (fabsf(u) > 0.001f) ? fmaxf(u, 0.0f) : quad;
}

// k permutation within a 16-half B row: qid-block q holds {2q,2q+1,2q+8,2q+9}
__device__ __host__ __forceinline__ int kpos(int k) {
    return (k < 8) ? ((k >> 1)*4 + (k & 1)) : (((k - 8) >> 1)*4 + 2 + (k & 1));
}

// A-region 16B XOR swizzle (conflict-free ldmatrix over 32B-stride rows)
__device__ __forceinline__ uint32_t swz(uint32_t off) {
    return off ^ ((off & 128u) >> 3);
}

__device__ __forceinline__ uint32_t smem_u32(const void* p) {
    return (uint32_t)__cvta_generic_to_shared(p);
}
__device__ __forceinline__ void lds64(uint32_t& a, uint32_t& b, uint32_t addr) {
    asm volatile("ld.shared.v2.b32 {%0,%1}, [%2];" : "=r"(a), "=r"(b) : "r"(addr));
}
__device__ __forceinline__ void ldmA(uint32_t* r, uint32_t addr) {
    asm volatile("ldmatrix.sync.aligned.m8n8.x4.shared.b16 {%0,%1,%2,%3}, [%4];"
        : "=r"(r[0]), "=r"(r[1]), "=r"(r[2]), "=r"(r[3]) : "r"(addr));
}
__device__ __forceinline__ void mma_f16(float* d, const uint32_t* a, const uint32_t* b) {
    asm("mma.sync.aligned.m16n8k16.row.col.f32.f16.f16.f32 "
        "{%0,%1,%2,%3}, {%4,%5,%6,%7}, {%8,%9}, {%0,%1,%2,%3};"
        : "+f"(d[0]), "+f"(d[1]), "+f"(d[2]), "+f"(d[3])
        : "r"(a[0]), "r"(a[1]), "r"(a[2]), "r"(a[3]), "r"(b[0]), "r"(b[1]));
}
__device__ __forceinline__ void cp16(uint32_t dst, const void* src, bool valid) {
    int sz = valid ? 16 : 0;
    asm volatile("cp.async.cg.shared.global [%0], [%1], 16, %2;"
                 :: "r"(dst), "l"(src), "r"(sz) : "memory");
}
#define CP_COMMIT() asm volatile("cp.async.commit_group;" ::: "memory")
#define CP_WAIT1()  asm volatile("cp.async.wait_group 1;" ::: "memory")
#define CP_WAIT0()  asm volatile("cp.async.wait_group 0;" ::: "memory")

// ---------------------------------------------------------------------------
// Weight repack: complex (wr, wi) -> fp16 [ci][tap][cout][k16], k-permuted
// ---------------------------------------------------------------------------
__global__ void repack_big(const float* __restrict__ wr, const float* __restrict__ wi,
                           const float* __restrict__ br, const float* __restrict__ bi,
                           int which) {
    __half* dw = (which == 1) ? g_w1 : g_w2;
    float*  db = (which == 1) ? g_b1 : g_b2;
    int idx = blockIdx.x * blockDim.x + threadIdx.x;
    if (idx < CC) db[idx] = (idx < FF) ? br[idx] : bi[idx - FF];
    if (idx >= NCH*9*CC*CHUNK) return;
    int k    = idx % CHUNK;
    int cout = (idx / CHUNK) % CC;
    int t    = (idx / (CHUNK*CC)) % 9;
    int ci   = idx / (CHUNK*CC*9);
    int cin = ci*CHUNK + k;
    int fo = cout % FF, fi = cin % FF;
    const float* src = ((cout < FF) == (cin < FF)) ? wr : wi;
    float v = src[(fo*FF + fi)*9 + t];
    if (cout < FF && cin >= FF) v = -v;
    dw[(idx - k) + kpos(k)] = __float2half_rn(v);
}

__global__ void repack_small(const float* __restrict__ wr, const float* __restrict__ wi,
                             const float* __restrict__ br, const float* __restrict__ bi) {
    int idx = blockIdx.x * blockDim.x + threadIdx.x;
    if (idx < CC) g_b0[idx] = (idx < FF) ? br[idx] : bi[idx - FF];
    if (idx >= 2*9*CC) return;
    int cout = idx % CC;
    int t    = (idx / CC) % 9;
    int cin  = idx / (9*CC);
    int fo = cout % FF;
    const float* src = ((cout < FF) == (cin == 0)) ? wr : wi;
    float v = src[fo*9 + t];
    if (cout < FF && cin == 1) v = -v;
    g_w0[idx] = v;
}

// ---------------------------------------------------------------------------
// Layer 0: conv 2 -> 96, exact fp32; writes out + g_sig0 (half, interleaved)
// ---------------------------------------------------------------------------
__global__ __launch_bounds__(256)
void conv0_kernel(const float* __restrict__ xr, const float* __restrict__ xi,
                  float* __restrict__ out) {
    __shared__ float sw[2*9*CC];
    __shared__ float sb[CC];
    for (int i = threadIdx.x; i < 2*9*CC; i += 256) sw[i] = g_w0[i];
    if (threadIdx.x < CC) sb[threadIdx.x] = g_b0[threadIdx.x];
    __syncthreads();

    int pix = blockIdx.x * 256 + threadIdx.x;
    if (pix >= BB*HWW) return;
    int b = pix / HWW;
    int p = pix - b*HWW;
    int y = p / WW, x = p - y*WW;

    const float* x0 = xr + b*HWW;
    const float* x1 = xi + b*HWW;
    float in[18];
    #pragma unroll
    for (int dy = 0; dy < 3; dy++) {
        #pragma unroll
        for (int dx = 0; dx < 3; dx++) {
            int yy = y + dy - 1, xx = x + dx - 1;
            bool ok = (yy >= 0) && (yy < HH) && (xx >= 0) && (xx < WW);
            in[dy*3 + dx]     = ok ? x0[yy*WW + xx] : 0.0f;
            in[9 + dy*3 + dx] = ok ? x1[yy*WW + xx] : 0.0f;
        }
    }

    for (int ci = 0; ci < NCH; ci++) {
        uint32_t u[8];
        #pragma unroll
        for (int j2 = 0; j2 < 8; j2++) {
            float a2[2];
            #pragma unroll
            for (int s = 0; s < 2; s++) {
                int cout = ci*CHUNK + 2*j2 + s;
                float acc = sb[cout];
                #pragma unroll
                for (int t = 0; t < 18; t++)
                    acc = fmaf(in[t], sw[t*CC + cout], acc);
                int f = cout % FF, c2 = cout / FF;
                out[((b*FF + f)*HWW + p)*2 + c2] = acc;
                a2[s] = sigma_f(acc);
            }
            __half2 hh = __floats2half2_rn(a2[0], a2[1]);
            u[j2] = *reinterpret_cast<uint32_t*>(&hh);
        }
        uint4* dst = reinterpret_cast<uint4*>(
            g_sig0 + ((size_t)(b*NCH + ci)*HWW + p)*CHUNK);
        dst[0] = make_uint4(u[0], u[1], u[2], u[3]);
        dst[1] = make_uint4(u[4], u[5], u[6], u[7]);
    }
}

// ---------------------------------------------------------------------------
// Layers 1,2: persistent-weight fp16 m16n8k16 implicit GEMM over 256-px strips.
// Grid = 148 CTAs x 256 thr (8 warps = 4M x 2N); warp tile m=64 px,
// n = {n0..n0+23} U {48+n0..}; A double-buffered cp.async (R10 scheme).
// Row-wrap at x=0/255-boundaries (x=0/319) repaired by fixup kernel.
// ---------------------------------------------------------------------------
template<int LAYER>
__global__ __launch_bounds__(256, 1)
void convT_kernel(float* __restrict__ out) {
    extern __shared__ __align__(256) char smem_raw[];
    uint32_t sb_base = smem_u32(smem_raw);
    uint32_t sa_base[2] = { sb_base + SA_OFF, sb_base + SA_OFF + ABUF_BYTES };
    __half* s_sig = reinterpret_cast<__half*>(smem_raw + SA_OFF);  // aliases A bufs

    const __half* __restrict__ sig_in = (LAYER == 1) ? g_sig0 : g_sig1;
    const __half* __restrict__ wg     = (LAYER == 1) ? g_w1 : g_w2;
    const float*  __restrict__ bg     = (LAYER == 1) ? g_b1 : g_b2;

    int tid  = threadIdx.x;
    int warp = tid >> 5, lane = tid & 31;
    int m0 = (warp >> 1) * 64;
    int n0 = (warp & 1) * 24;
    int gid = lane >> 2, qid = lane & 3;
    int arow = lane & 15;
    uint32_t akoff = (uint32_t)(lane >> 4) * 16;

    // stage ALL weights once (flat memcpy; k-perm pre-baked)
    {
        const uint4* srcw = reinterpret_cast<const uint4*>(wg);
        uint4* dstw = reinterpret_cast<uint4*>(smem_raw);
        for (int i = tid; i < SB_BYTES/16; i += 256) dstw[i] = srcw[i];
    }

    // hoisted biases for this warp's n-tile
    float brl[3][2], bil[3][2];
    #pragma unroll
    for (int nt = 0; nt < 3; nt++) {
        int n = n0 + nt*8 + 2*qid;
        brl[nt][0] = __ldg(bg + n);      brl[nt][1] = __ldg(bg + n + 1);
        bil[nt][0] = __ldg(bg + n + 48); bil[nt][1] = __ldg(bg + n + 49);
    }
    __syncthreads();

    for (int job = blockIdx.x; job < NJOBS; job += gridDim.x) {
        int b     = job / NSTRIP;
        int base  = (job - b*NSTRIP) * STRIP;
        const __half* plane0 = sig_in + (size_t)b*NCH*HWW*CHUNK;

        float acc[4][6][4];
        #pragma unroll
        for (int h = 0; h < 4; h++)
            #pragma unroll
            for (int nt = 0; nt < 6; nt++)
                #pragma unroll
                for (int r = 0; r < 4; r++) acc[h][nt][r] = 0.0f;

        // prefetch chunk 0 into buffer 0
        {
            const __half* pc = plane0;
            for (int i = tid; i < 2*AROWS; i += 256) {
                int blk = i >> 1, hi = i & 1;
                int dyr = blk / 258, px = blk - dyr*258;
                int fl  = base + (dyr - 1)*WW + px - 1;
                bool ok = (fl >= 0) && (fl < HWW);
                cp16(sa_base[0] + swz((uint32_t)(blk*32 + hi*16)),
                     pc + ((size_t)(ok ? fl : 0))*CHUNK + hi*8, ok);
            }
        }
        CP_COMMIT();

        for (int ci = 0; ci < NCH; ci++) {
            if (ci + 1 < NCH) {
                const __half* pc = plane0 + (size_t)(ci+1)*HWW*CHUNK;
                uint32_t ab = sa_base[(ci+1) & 1];
                for (int i = tid; i < 2*AROWS; i += 256) {
                    int blk = i >> 1, hi = i & 1;
                    int dyr = blk / 258, px = blk - dyr*258;
                    int fl  = base + (dyr - 1)*WW + px - 1;
                    bool ok = (fl >= 0) && (fl < HWW);
                    cp16(ab + swz((uint32_t)(blk*32 + hi*16)),
                         pc + ((size_t)(ok ? fl : 0))*CHUNK + hi*8, ok);
                }
                CP_COMMIT();
                CP_WAIT1();
            } else {
                CP_WAIT0();
            }
            __syncthreads();

            uint32_t sa = sa_base[ci & 1];
            uint32_t cioff = (uint32_t)ci * (9*CC*32);
            #pragma unroll
            for (int tap = 0; tap < 9; tap++) {
                int dy = tap / 3, dx = tap - dy*3;
                uint32_t boff = cioff + (uint32_t)tap * (CC*32);
                uint32_t bf[6][2];
                #pragma unroll
                for (int nt = 0; nt < 6; nt++) {
                    int nrow = ((nt < 3) ? (n0 + nt*8) : (48 + n0 + (nt-3)*8)) + gid;
                    lds64(bf[nt][0], bf[nt][1],
                          sb_base + boff + (uint32_t)nrow*32 + (uint32_t)qid*8);
                }
                #pragma unroll
                for (int h = 0; h < 4; h++) {
                    int p = dy*258 + dx + m0 + h*16 + arow;
                    uint32_t a[4];
                    ldmA(a, sa + swz((uint32_t)p*32 + akoff));
                    #pragma unroll
                    for (int nt = 0; nt < 6; nt++)
                        mma_f16(acc[h][nt], a, bf[nt]);
                }
            }
            __syncthreads();   // all MMA reads done before buffer reuse / s_sig
        }

        // --- epilogue: direct float2 stores from fragments ---
        float2* ob = reinterpret_cast<float2*>(out)
                   + (size_t)(LAYER*BB + b)*FF*HWW + base;
        #pragma unroll
        for (int h = 0; h < 4; h++) {
            int m = m0 + h*16 + gid;
            #pragma unroll
            for (int nt = 0; nt < 3; nt++) {
                int n = n0 + nt*8 + 2*qid;
                float re0 = acc[h][nt][0] + brl[nt][0], re1 = acc[h][nt][1] + brl[nt][1];
                float re2 = acc[h][nt][2] + brl[nt][0], re3 = acc[h][nt][3] + brl[nt][1];
                float im0 = acc[h][nt+3][0] + bil[nt][0], im1 = acc[h][nt+3][1] + bil[nt][1];
                float im2 = acc[h][nt+3][2] + bil[nt][0], im3 = acc[h][nt+3][3] + bil[nt][1];
                ob[(size_t)n*HWW + m]         = make_float2(re0, im0);
                ob[(size_t)(n+1)*HWW + m]     = make_float2(re1, im1);
                ob[(size_t)n*HWW + m + 8]     = make_float2(re2, im2);
                ob[(size_t)(n+1)*HWW + m + 8] = make_float2(re3, im3);
                if (LAYER == 1) {
                    __half2* sg;
                    sg = reinterpret_cast<__half2*>(s_sig + m*CC + n);
                    *sg = __floats2half2_rn(sigma_f(re0), sigma_f(re1));
                    sg = reinterpret_cast<__half2*>(s_sig + m*CC + n + 48);
                    *sg = __floats2half2_rn(sigma_f(im0), sigma_f(im1));
                    sg = reinterpret_cast<__half2*>(s_sig + (m+8)*CC + n);
                    *sg = __floats2half2_rn(sigma_f(re2), sigma_f(re3));
                    sg = reinterpret_cast<__half2*>(s_sig + (m+8)*CC + n + 48);
                    *sg = __floats2half2_rn(sigma_f(im2), sigma_f(im3));
                }
            }
        }
        if (LAYER == 1) {
            __syncthreads();   // s_sig complete across warps
            for (int i = tid; i < NCH*STRIP; i += 256) {
                int ci = i >> 8;
                int px = i & (STRIP-1);
                const uint4* srcv = reinterpret_cast<const uint4*>(
                    s_sig + px*CC + ci*CHUNK);
                uint4* dst = reinterpret_cast<uint4*>(
                    g_sig1 + ((size_t)(b*NCH + ci)*HWW + base + px)*CHUNK);
                dst[0] = srcv[0];
                dst[1] = srcv[1];
            }
            __syncthreads();   // s_sig (A-buffer alias) free before next prefetch
        }
    }
}

// ---------------------------------------------------------------------------
// Border fixup: recompute columns x=0 and x=319 for layer L (x-wrap repair).
// ---------------------------------------------------------------------------
template<int LAYER>
__global__ __launch_bounds__(96)
void fixup_kernel(float* __restrict__ out) {
    const __half* __restrict__ sig_in = (LAYER == 1) ? g_sig0 : g_sig1;
    const __half* __restrict__ wg     = (LAYER == 1) ? g_w1 : g_w2;
    const float*  __restrict__ bg     = (LAYER == 1) ? g_b1 : g_b2;

    int blk  = blockIdx.x;
    int side = blk & 1;
    int y    = (blk >> 1) % HH;
    int b    = (blk >> 1) / HH;
    int x    = side ? (WW-1) : 0;
    int xs   = side ? (WW-2) : 0;
    int cout = threadIdx.x;

    __shared__ float s_act[3][2][CC];
    for (int i = cout; i < 3*2*CC; i += 96) {
        int c   = i % CC;
        int dxl = (i / CC) % 2;
        int dy  = i / (2*CC);
        int yy  = y + dy - 1;
        float v = 0.0f;
        if (yy >= 0 && yy < HH)
            v = __half2float(sig_in[((size_t)(b*NCH + c/CHUNK)*HWW
                                     + yy*WW + xs + dxl)*CHUNK + (c % CHUNK)]);
        s_act[dy][dxl][c] = v;
    }
    __syncthreads();

    float acc = bg[cout];
    #pragma unroll
    for (int dy = 0; dy < 3; dy++)
        #pragma unroll
        for (int dx = 0; dx < 3; dx++) {
            int xx = x + dx - 1;
            if (xx < 0 || xx >= WW) continue;
            int dxl = xx - xs;
            for (int c = 0; c < CC; c++) {
                int row = ((c/CHUNK)*9 + dy*3 + dx)*CC + cout;
                float w = __half2float(wg[row*CHUNK + kpos(c % CHUNK)]);
                acc = fmaf(w, s_act[dy][dxl][c], acc);
            }
        }

    int p = y*WW + x;
    if (LAYER == 1)
        g_sig1[((size_t)(b*NCH + cout/CHUNK)*HWW + p)*CHUNK + (cout % CHUNK)]
            = __float2half_rn(sigma_f(acc));
    int f = cout % FF, c2 = cout / FF;
    out[(((size_t)(LAYER*BB + b)*FF + f)*HWW + p)*2 + c2] = acc;
}

extern "C" void kernel_launch(void* const* d_in, const int* in_sizes, int n_in,
                              void* d_out, int out_size) {
    const float* x_real = (const float*)d_in[0];
    const float* x_imag = (const float*)d_in[1];
    const float* w0r = (const float*)d_in[2];
    const float* w0i = (const float*)d_in[3];
    const float* b0r = (const float*)d_in[4];
    const float* b0i = (const float*)d_in[5];
    const float* w1r = (const float*)d_in[6];
    const float* w1i = (const float*)d_in[7];
    const float* b1r = (const float*)d_in[8];
    const float* b1i = (const float*)d_in[9];
    const float* w2r = (const float*)d_in[10];
    const float* w2i = (const float*)d_in[11];
    const float* b2r = (const float*)d_in[12];
    const float* b2i = (const float*)d_in[13];
    float* out = (float*)d_out;

    static bool attr_set = false;
    if (!attr_set) {
        cudaFuncSetAttribute(convT_kernel<1>, cudaFuncAttributeMaxDynamicSharedMemorySize, SMEM_BYTES);
        cudaFuncSetAttribute(convT_kernel<2>, cudaFuncAttributeMaxDynamicSharedMemorySize, SMEM_BYTES);
        attr_set = true;
    }

    repack_small<<<(2*9*CC + 255)/256, 256>>>(w0r, w0i, b0r, b0i);
    repack_big<<<(NCH*9*CC*CHUNK + 255)/256, 256>>>(w1r, w1i, b1r, b1i, 1);
    repack_big<<<(NCH*9*CC*CHUNK + 255)/256, 256>>>(w2r, w2i, b2r, b2i, 2);

    conv0_kernel<<<(BB*HWW + 255)/256, 256>>>(x_real, x_imag, out);

    convT_kernel<1><<<NCTAS, 256, SMEM_BYTES>>>(out);
    fixup_kernel<1><<<BB*HH*2, 96>>>(out);
    convT_kernel<2><<<NCTAS, 256, SMEM_BYTES>>>(out);
    fixup_kernel<2><<<BB*HH*2, 96>>>(out);
}

// round 13
// speedup vs baseline: 1.0090x; 1.0090x over previous
#include <cuda_runtime.h>
#include <cuda_fp16.h>
#include <cstdint>

#define BB 2
#define FF 48
#define CC 96
#define HH 320
#define WW 320
#define HWW (HH*WW)

#define STRIP 128
#define NSTRIP (HWW/STRIP)   // 800
#define NJOBS (NSTRIP*BB)    // 1600
#define CHUNK 16
#define NCH (CC/CHUNK)       // 6
#define NCTAS 148

// smem: B weights (k-permuted rows, unswizzled) at 0 | two A buffers (XOR-swizzled)
// s_sig aliases the A buffers (R10 scheme).
#define SB_BYTES (NCH*9*CC*32)          // 165888
#define ABUF_BYTES 12800                // 390 rows * 32B, padded to 256B mult
#define SA_OFF SB_BYTES
#define SMEM_BYTES (SB_BYTES + 2*ABUF_BYTES)   // 191488
#define SSIG_OFF SB_BYTES               // 24576B needed <= 25600 available

// sigma'd activations, fp16, pixel-interleaved by 16-ch chunk: [b][ci][pix][k16]
__device__ __align__(16) __half g_sig0[(size_t)BB*NCH*HWW*CHUNK];
__device__ __align__(16) __half g_sig1[(size_t)BB*NCH*HWW*CHUNK];
// weights: fp16, [ci][tap][cout96][k16], k-permuted per 16-half row
__device__ float  g_w0[2*9*CC];
__device__ __align__(16) __half g_w1[NCH*9*CC*CHUNK];
__device__ __align__(16) __half g_w2[NCH*9*CC*CHUNK];
__device__ float g_b0[CC];
__device__ float g_b1[CC];
__device__ float g_b2[CC];

__device__ __forceinline__ float sigma_f(float u) {
    float quad = fmaf(u, fmaf(u, 250.0f, 0.5f), 0.00025f);
    return (fabsf(u) > 0.001f) ? fmaxf(u, 0.0f) : quad;
}

// k permutation within a 16-half B row: qid-block q holds {2q,2q+1,2q+8,2q+9}
__device__ __host__ __forceinline__ int kpos(int k) {
    return (k < 8) ? ((k >> 1)*4 + (k & 1)) : (((k - 8) >> 1)*4 + 2 + (k & 1));
}

// A-region 16B XOR swizzle (conflict-free ldmatrix over 32B-stride rows)
__device__ __forceinline__ uint32_t swz(uint32_t off) {
    return off ^ ((off & 128u) >> 3);
}

__device__ __forceinline__ uint32_t smem_u32(const void* p) {
    return (uint32_t)__cvta_generic_to_shared(p);
}
__device__ __forceinline__ void lds64(uint32_t& a, uint32_t& b, uint32_t addr) {
    asm volatile("ld.shared.v2.b32 {%0,%1}, [%2];" : "=r"(a), "=r"(b) : "r"(addr));
}
__device__ __forceinline__ void ldmA(uint32_t* r, uint32_t addr) {
    asm volatile("ldmatrix.sync.aligned.m8n8.x4.shared.b16 {%0,%1,%2,%3}, [%4];"
        : "=r"(r[0]), "=r"(r[1]), "=r"(r[2]), "=r"(r[3]) : "r"(addr));
}
__device__ __forceinline__ void mma_f16(float* d, const uint32_t* a, const uint32_t* b) {
    asm("mma.sync.aligned.m16n8k16.row.col.f32.f16.f16.f32 "
        "{%0,%1,%2,%3}, {%4,%5,%6,%7}, {%8,%9}, {%0,%1,%2,%3};"
        : "+f"(d[0]), "+f"(d[1]), "+f"(d[2]), "+f"(d[3])
        : "r"(a[0]), "r"(a[1]), "r"(a[2]), "r"(a[3]), "r"(b[0]), "r"(b[1]));
}
__device__ __forceinline__ void cp16(uint32_t dst, const void* src, bool valid) {
    int sz = valid ? 16 : 0;
    asm volatile("cp.async.cg.shared.global [%0], [%1], 16, %2;"
                 :: "r"(dst), "l"(src), "r"(sz) : "memory");
}
#define CP_COMMIT() asm volatile("cp.async.commit_group;" ::: "memory")
#define CP_WAIT1()  asm volatile("cp.async.wait_group 1;" ::: "memory")
#define CP_WAIT0()  asm volatile("cp.async.wait_group 0;" ::: "memory")

// ---------------------------------------------------------------------------
// Weight repack: complex (wr, wi) -> fp16 [ci][tap][cout][k16], k-permuted
// ---------------------------------------------------------------------------
__global__ void repack_big(const float* __restrict__ wr, const float* __restrict__ wi,
                           const float* __restrict__ br, const float* __restrict__ bi,
                           int which) {
    __half* dw = (which == 1) ? g_w1 : g_w2;
    float*  db = (which == 1) ? g_b1 : g_b2;
    int idx = blockIdx.x * blockDim.x + threadIdx.x;
    if (idx < CC) db[idx] = (idx < FF) ? br[idx] : bi[idx - FF];
    if (idx >= NCH*9*CC*CHUNK) return;
    int k    = idx % CHUNK;
    int cout = (idx / CHUNK) % CC;
    int t    = (idx / (CHUNK*CC)) % 9;
    int ci   = idx / (CHUNK*CC*9);
    int cin = ci*CHUNK + k;
    int fo = cout % FF, fi = cin % FF;
    const float* src = ((cout < FF) == (cin < FF)) ? wr : wi;
    float v = src[(fo*FF + fi)*9 + t];
    if (cout < FF && cin >= FF) v = -v;
    dw[(idx - k) + kpos(k)] = __float2half_rn(v);
}

__global__ void repack_small(const float* __restrict__ wr, const float* __restrict__ wi,
                             const float* __restrict__ br, const float* __restrict__ bi) {
    int idx = blockIdx.x * blockDim.x + threadIdx.x;
    if (idx < CC) g_b0[idx] = (idx < FF) ? br[idx] : bi[idx - FF];
    if (idx >= 2*9*CC) return;
    int cout = idx % CC;
    int t    = (idx / CC) % 9;
    int cin  = idx / (9*CC);
    int fo = cout % FF;
    const float* src = ((cout < FF) == (cin == 0)) ? wr : wi;
    float v = src[fo*9 + t];
    if (cout < FF && cin == 1) v = -v;
    g_w0[idx] = v;
}

// ---------------------------------------------------------------------------
// Layer 0: conv 2 -> 96, exact fp32; paired (re,im) float2 output stores.
// Writes out + g_sig0 (half, interleaved by 16-ch chunk).
// ---------------------------------------------------------------------------
__global__ __launch_bounds__(256)
void conv0_kernel(const float* __restrict__ xr, const float* __restrict__ xi,
                  float* __restrict__ out) {
    __shared__ float sw[2*9*CC];
    __shared__ float sb[CC];
    for (int i = threadIdx.x; i < 2*9*CC; i += 256) sw[i] = g_w0[i];
    if (threadIdx.x < CC) sb[threadIdx.x] = g_b0[threadIdx.x];
    __syncthreads();

    int pix = blockIdx.x * 256 + threadIdx.x;
    if (pix >= BB*HWW) return;
    int b = pix / HWW;
    int p = pix - b*HWW;
    int y = p / WW, x = p - y*WW;

    const float* x0 = xr + b*HWW;
    const float* x1 = xi + b*HWW;
    float in[18];
    #pragma unroll
    for (int dy = 0; dy < 3; dy++) {
        #pragma unroll
        for (int dx = 0; dx < 3; dx++) {
            int yy = y + dy - 1, xx = x + dx - 1;
            bool ok = (yy >= 0) && (yy < HH) && (xx >= 0) && (xx < WW);
            in[dy*3 + dx]     = ok ? x0[yy*WW + xx] : 0.0f;
            in[9 + dy*3 + dx] = ok ? x1[yy*WW + xx] : 0.0f;
        }
    }

    float2* ob = reinterpret_cast<float2*>(out) + (size_t)b*FF*HWW + p;
    for (int ci = 0; ci < 3; ci++) {            // real chunk ci pairs imag chunk ci+3
        uint32_t ur[8], ui[8];
        #pragma unroll
        for (int j2 = 0; j2 < 8; j2++) {
            float r2[2], i2[2];
            #pragma unroll
            for (int s = 0; s < 2; s++) {
                int f = ci*CHUNK + 2*j2 + s;
                float accR = sb[f], accI = sb[f + FF];
                #pragma unroll
                for (int t = 0; t < 18; t++) {
                    accR = fmaf(in[t], sw[t*CC + f],      accR);
                    accI = fmaf(in[t], sw[t*CC + f + FF], accI);
                }
                ob[(size_t)f*HWW] = make_float2(accR, accI);
                r2[s] = sigma_f(accR);
                i2[s] = sigma_f(accI);
            }
            __half2 hr = __floats2half2_rn(r2[0], r2[1]);
            __half2 hi = __floats2half2_rn(i2[0], i2[1]);
            ur[j2] = *reinterpret_cast<uint32_t*>(&hr);
            ui[j2] = *reinterpret_cast<uint32_t*>(&hi);
        }
        uint4* dr = reinterpret_cast<uint4*>(
            g_sig0 + ((size_t)(b*NCH + ci)*HWW + p)*CHUNK);
        dr[0] = make_uint4(ur[0], ur[1], ur[2], ur[3]);
        dr[1] = make_uint4(ur[4], ur[5], ur[6], ur[7]);
        uint4* di = reinterpret_cast<uint4*>(
            g_sig0 + ((size_t)(b*NCH + ci + 3)*HWW + p)*CHUNK);
        di[0] = make_uint4(ui[0], ui[1], ui[2], ui[3]);
        di[1] = make_uint4(ui[4], ui[5], ui[6], ui[7]);
    }
}

// ---------------------------------------------------------------------------
// Layers 1,2: persistent-weight fp16 m16n8k16 implicit GEMM (R10 skeleton).
// Grid = 148 CTAs x 256 thr (8 warps = 4M x 2N); warp tile m=32 px,
// n = {n0..n0+23} U {48+n0..}; A double-buffered cp.async, two syncs/chunk.
// B fragments: single LDS.64 per (nt) via k-permuted rows.
// Row-wrap at x=0/319 wrong by construction -> fixup repairs.
// ---------------------------------------------------------------------------
template<int LAYER>
__global__ __launch_bounds__(256, 1)
void convT_kernel(float* __restrict__ out) {
    extern __shared__ __align__(256) char smem_raw[];
    uint32_t sb_base = smem_u32(smem_raw);
    uint32_t sa_base[2] = { sb_base + SA_OFF, sb_base + SA_OFF + ABUF_BYTES };
    __half* s_sig = reinterpret_cast<__half*>(smem_raw + SSIG_OFF);

    const __half* __restrict__ sig_in = (LAYER == 1) ? g_sig0 : g_sig1;
    const __half* __restrict__ wg     = (LAYER == 1) ? g_w1 : g_w2;
    const float*  __restrict__ bg     = (LAYER == 1) ? g_b1 : g_b2;

    int tid  = threadIdx.x;
    int warp = tid >> 5, lane = tid & 31;
    int m0 = (warp >> 1) * 32;
    int n0 = (warp & 1) * 24;
    int gid = lane >> 2, qid = lane & 3;
    int arow = lane & 15;
    uint32_t akoff = (uint32_t)(lane >> 4) * 16;

    // stage ALL weights once (flat memcpy; k-perm pre-baked)
    {
        const uint4* srcw = reinterpret_cast<const uint4*>(wg);
        uint4* dstw = reinterpret_cast<uint4*>(smem_raw);
        for (int i = tid; i < SB_BYTES/16; i += 256) dstw[i] = srcw[i];
    }
    __syncthreads();

    for (int job = blockIdx.x; job < NJOBS; job += gridDim.x) {
        int b     = job / NSTRIP;
        int strip = job - b*NSTRIP;
        int base  = strip * STRIP;
        const __half* plane0 = sig_in + (size_t)b*NCH*HWW*CHUNK;

        float acc[2][6][4];
        #pragma unroll
        for (int h = 0; h < 2; h++)
            #pragma unroll
            for (int nt = 0; nt < 6; nt++)
                #pragma unroll
                for (int r = 0; r < 4; r++) acc[h][nt][r] = 0.0f;

        // prefetch chunk 0
        {
            const __half* pc = plane0;
            for (int i = tid; i < 2*390; i += 256) {
                int blk = i >> 1, hi = i & 1;
                int dyr = blk / 130, px = blk - dyr*130;
                int fl  = base + (dyr - 1)*WW + px - 1;
                bool ok = (fl >= 0) && (fl < HWW);
                cp16(sa_base[0] + swz((uint32_t)(blk*32 + hi*16)),
                     pc + ((size_t)(ok ? fl : 0))*CHUNK + hi*8, ok);
            }
        }
        CP_COMMIT();

        for (int ci = 0; ci < NCH; ci++) {
            if (ci + 1 < NCH) {
                const __half* pc = plane0 + (size_t)(ci+1)*HWW*CHUNK;
                uint32_t ab = sa_base[(ci+1) & 1];
                for (int i = tid; i < 2*390; i += 256) {
                    int blk = i >> 1, hi = i & 1;
                    int dyr = blk / 130, px = blk - dyr*130;
                    int fl  = base + (dyr - 1)*WW + px - 1;
                    bool ok = (fl >= 0) && (fl < HWW);
                    cp16(ab + swz((uint32_t)(blk*32 + hi*16)),
                         pc + ((size_t)(ok ? fl : 0))*CHUNK + hi*8, ok);
                }
                CP_COMMIT();
                CP_WAIT1();
            } else {
                CP_WAIT0();
            }
            __syncthreads();

            uint32_t sa = sa_base[ci & 1];
            uint32_t cioff = (uint32_t)ci * (9*CC*32);
            #pragma unroll
            for (int tap = 0; tap < 9; tap++) {
                int dy = tap / 3, dx = tap - dy*3;
                uint32_t boff = cioff + (uint32_t)tap * (CC*32);
                uint32_t bf[6][2];
                #pragma unroll
                for (int nt = 0; nt < 6; nt++) {
                    int nrow = ((nt < 3) ? (n0 + nt*8) : (48 + n0 + (nt-3)*8)) + gid;
                    lds64(bf[nt][0], bf[nt][1],
                          sb_base + boff + (uint32_t)nrow*32 + (uint32_t)qid*8);
                }
                #pragma unroll
                for (int h = 0; h < 2; h++) {
                    int p = dy*130 + dx + m0 + h*16 + arow;
                    uint32_t a[4];
                    ldmA(a, sa + swz((uint32_t)p*32 + akoff));
                    #pragma unroll
                    for (int nt = 0; nt < 6; nt++)
                        mma_f16(acc[h][nt], a, bf[nt]);
                }
            }
            __syncthreads();
        }

        // --- epilogue: direct float2 stores from fragments ---
        float2* ob = reinterpret_cast<float2*>(out)
                   + (size_t)(LAYER*BB + b)*FF*HWW + base;
        #pragma unroll
        for (int h = 0; h < 2; h++) {
            int m = m0 + h*16 + gid;
            #pragma unroll
            for (int nt = 0; nt < 3; nt++) {
                int n = n0 + nt*8 + 2*qid;
                float br0 = __ldg(bg + n),      br1 = __ldg(bg + n + 1);
                float bi0 = __ldg(bg + n + 48), bi1 = __ldg(bg + n + 49);
                float re0 = acc[h][nt][0] + br0, re1 = acc[h][nt][1] + br1;
                float re2 = acc[h][nt][2] + br0, re3 = acc[h][nt][3] + br1;
                float im0 = acc[h][nt+3][0] + bi0, im1 = acc[h][nt+3][1] + bi1;
                float im2 = acc[h][nt+3][2] + bi0, im3 = acc[h][nt+3][3] + bi1;
                ob[(size_t)n*HWW + m]         = make_float2(re0, im0);
                ob[(size_t)(n+1)*HWW + m]     = make_float2(re1, im1);
                ob[(size_t)n*HWW + m + 8]     = make_float2(re2, im2);
                ob[(size_t)(n+1)*HWW + m + 8] = make_float2(re3, im3);
                if (LAYER == 1) {
                    __half2* sg;
                    sg = reinterpret_cast<__half2*>(s_sig + m*CC + n);
                    *sg = __floats2half2_rn(sigma_f(re0), sigma_f(re1));
                    sg = reinterpret_cast<__half2*>(s_sig + m*CC + n + 48);
                    *sg = __floats2half2_rn(sigma_f(im0), sigma_f(im1));
                    sg = reinterpret_cast<__half2*>(s_sig + (m+8)*CC + n);
                    *sg = __floats2half2_rn(sigma_f(re2), sigma_f(re3));
                    sg = reinterpret_cast<__half2*>(s_sig + (m+8)*CC + n + 48);
                    *sg = __floats2half2_rn(sigma_f(im2), sigma_f(im3));
                }
            }
        }
        if (LAYER == 1) {
            __syncthreads();   // s_sig complete across warps
            for (int i = tid; i < NCH*STRIP; i += 256) {
                int ci = i >> 7;
                int px = i & (STRIP-1);
                const uint4* srcv = reinterpret_cast<const uint4*>(
                    s_sig + px*CC + ci*CHUNK);
                uint4* dst = reinterpret_cast<uint4*>(
                    g_sig1 + ((size_t)(b*NCH + ci)*HWW + base + px)*CHUNK);
                dst[0] = srcv[0];
                dst[1] = srcv[1];
            }
            __syncthreads();   // s_sig aliases A buffers: done before next prefetch
        }
    }
}

// ---------------------------------------------------------------------------
// Border fixup: recompute columns x=0 and x=319 for layer L (x-wrap repair).
// ---------------------------------------------------------------------------
template<int LAYER>
__global__ __launch_bounds__(96)
void fixup_kernel(float* __restrict__ out) {
    const __half* __restrict__ sig_in = (LAYER == 1) ? g_sig0 : g_sig1;
    const __half* __restrict__ wg     = (LAYER == 1) ? g_w1 : g_w2;
    const float*  __restrict__ bg     = (LAYER == 1) ? g_b1 : g_b2;

    int blk  = blockIdx.x;
    int side = blk & 1;
    int y    = (blk >> 1) % HH;
    int b    = (blk >> 1) / HH;
    int x    = side ? (WW-1) : 0;
    int xs   = side ? (WW-2) : 0;
    int cout = threadIdx.x;

    __shared__ float s_act[3][2][CC];
    for (int i = cout; i < 3*2*CC; i += 96) {
        int c   = i % CC;
        int dxl = (i / CC) % 2;
        int dy  = i / (2*CC);
        int yy  = y + dy - 1;
        float v = 0.0f;
        if (yy >= 0 && yy < HH)
            v = __half2float(sig_in[((size_t)(b*NCH + c/CHUNK)*HWW
                                     + yy*WW + xs + dxl)*CHUNK + (c % CHUNK)]);
        s_act[dy][dxl][c] = v;
    }
    __syncthreads();

    float acc = bg[cout];
    #pragma unroll
    for (int dy = 0; dy < 3; dy++)
        #pragma unroll
        for (int dx = 0; dx < 3; dx++) {
            int xx = x + dx - 1;
            if (xx < 0 || xx >= WW) continue;
            int dxl = xx - xs;
            for (int c = 0; c < CC; c++) {
                int row = ((c/CHUNK)*9 + dy*3 + dx)*CC + cout;
                float w = __half2float(wg[row*CHUNK + kpos(c % CHUNK)]);
                acc = fmaf(w, s_act[dy][dxl][c], acc);
            }
        }

    int p = y*WW + x;
    if (LAYER == 1)
        g_sig1[((size_t)(b*NCH + cout/CHUNK)*HWW + p)*CHUNK + (cout % CHUNK)]
            = __float2half_rn(sigma_f(acc));
    int f = cout % FF, c2 = cout / FF;
    out[(((size_t)(LAYER*BB + b)*FF + f)*HWW + p)*2 + c2] = acc;
}

extern "C" void kernel_launch(void* const* d_in, const int* in_sizes, int n_in,
                              void* d_out, int out_size) {
    const float* x_real = (const float*)d_in[0];
    const float* x_imag = (const float*)d_in[1];
    const float* w0r = (const float*)d_in[2];
    const float* w0i = (const float*)d_in[3];
    const float* b0r = (const float*)d_in[4];
    const float* b0i = (const float*)d_in[5];
    const float* w1r = (const float*)d_in[6];
    const float* w1i = (const float*)d_in[7];
    const float* b1r = (const float*)d_in[8];
    const float* b1i = (const float*)d_in[9];
    const float* w2r = (const float*)d_in[10];
    const float* w2i = (const float*)d_in[11];
    const float* b2r = (const float*)d_in[12];
    const float* b2i = (const float*)d_in[13];
    float* out = (float*)d_out;

    static bool attr_set = false;
    if (!attr_set) {
        cudaFuncSetAttribute(convT_kernel<1>, cudaFuncAttributeMaxDynamicSharedMemorySize, SMEM_BYTES);
        cudaFuncSetAttribute(convT_kernel<2>, cudaFuncAttributeMaxDynamicSharedMemorySize, SMEM_BYTES);
        attr_set = true;
    }

    repack_small<<<(2*9*CC + 255)/256, 256>>>(w0r, w0i, b0r, b0i);
    repack_big<<<(NCH*9*CC*CHUNK + 255)/256, 256>>>(w1r, w1i, b1r, b1i, 1);
    repack_big<<<(NCH*9*CC*CHUNK + 255)/256, 256>>>(w2r, w2i, b2r, b2i, 2);

    conv0_kernel<<<(BB*HWW + 255)/256, 256>>>(x_real, x_imag, out);

    convT_kernel<1><<<NCTAS, 256, SMEM_BYTES>>>(out);
    fixup_kernel<1><<<BB*HH*2, 96>>>(out);
    convT_kernel<2><<<NCTAS, 256, SMEM_BYTES>>>(out);
    fixup_kernel<2><<<BB*HH*2, 96>>>(out);
}

// round 14
// speedup vs baseline: 1.0805x; 1.0708x over previous
#include <cuda_runtime.h>
#include <cuda_fp16.h>
#include <cstdint>

#define BB 2
#define FF 48
#define CC 96
#define HH 320
#define WW 320
#define HWW (HH*WW)

#define STRIP 128
#define NSTRIP (HWW/STRIP)   // 800
#define NJOBS (NSTRIP*BB)    // 1600
#define CHUNK 16
#define NCH (CC/CHUNK)       // 6
#define NCTAS 148

// smem: B (all weights) at 0, then two A buffers; s_sig aliases A buffers.
#define SB_BYTES (NCH*9*CC*32)          // 165888 (rows of 32B, XOR-swizzled)
#define ABUF_BYTES 12800                // 390 rows * 32B = 12480, padded to 256B mult
#define SA_OFF SB_BYTES                 // 165888 (256B aligned)
#define SMEM_BYTES (SB_BYTES + 2*ABUF_BYTES)   // 191488
#define SSIG_OFF SB_BYTES               // 24576B needed <= 25600 available

// sigma'd activations, fp16, pixel-interleaved by 16-ch chunk: [b][ci][pix][k16]
__device__ __align__(16) __half g_sig0[(size_t)BB*NCH*HWW*CHUNK];
__device__ __align__(16) __half g_sig1[(size_t)BB*NCH*HWW*CHUNK];
// weights: fp16, [ci][tap][cout96][k16] with 16B XOR swizzle pre-baked
__device__ float  g_w0[2*9*CC];
__device__ __align__(16) __half g_w1[NCH*9*CC*CHUNK];
__device__ __align__(16) __half g_w2[NCH*9*CC*CHUNK];
__device__ float g_b0[CC];
__device__ float g_b1[CC];
__device__ float g_b2[CC];

__device__ __forceinline__ float sigma_f(float u) {
    float quad = fmaf(u, fmaf(u, 250.0f, 0.5f), 0.00025f);
    return (fabsf(u) > 0.001f) ? fmaxf(u, 0.0f) : quad;
}

// 16B XOR swizzle on byte offsets within a 256B-aligned region:
// rows (32B) with bit2 set swap their two 16B halves -> conflict-free LDS/ldmatrix
__device__ __forceinline__ uint32_t swz(uint32_t off) {
    return off ^ ((off & 128u) >> 3);
}
__device__ __host__ __forceinline__ int swz_half_idx(int h) {   // same transform on half index
    return h ^ ((h >> 3) & 8);
}

__device__ __forceinline__ uint32_t smem_u32(const void* p) {
    return (uint32_t)__cvta_generic_to_shared(p);
}
__device__ __forceinline__ uint32_t lds32(uint32_t addr) {
    uint32_t v; asm volatile("ld.shared.b32 %0, [%1];" : "=r"(v) : "r"(addr)); return v;
}
__device__ __forceinline__ void ldmA(uint32_t* r, uint32_t addr) {
    asm volatile("ldmatrix.sync.aligned.m8n8.x4.shared.b16 {%0,%1,%2,%3}, [%4];"
        : "=r"(r[0]), "=r"(r[1]), "=r"(r[2]), "=r"(r[3]) : "r"(addr));
}
__device__ __forceinline__ void mma_f16(float* d, const uint32_t* a, const uint32_t* b) {
    asm("mma.sync.aligned.m16n8k16.row.col.f32.f16.f16.f32 "
        "{%0,%1,%2,%3}, {%4,%5,%6,%7}, {%8,%9}, {%0,%1,%2,%3};"
        : "+f"(d[0]), "+f"(d[1]), "+f"(d[2]), "+f"(d[3])
        : "r"(a[0]), "r"(a[1]), "r"(a[2]), "r"(a[3]), "r"(b[0]), "r"(b[1]));
}
__device__ __forceinline__ void cp16(uint32_t dst, const void* src, bool valid) {
    int sz = valid ? 16 : 0;
    asm volatile("cp.async.cg.shared.global [%0], [%1], 16, %2;"
                 :: "r"(dst), "l"(src), "r"(sz) : "memory");
}
#define CP_COMMIT() asm volatile("cp.async.commit_group;" ::: "memory")
#define CP_WAIT1()  asm volatile("cp.async.wait_group 1;" ::: "memory")
#define CP_WAIT0()  asm volatile("cp.async.wait_group 0;" ::: "memory")

// ---------------------------------------------------------------------------
// Weight repack: complex (wr, wi) -> fp16 [ci][tap][cout][k16], swizzle baked
// ---------------------------------------------------------------------------
__global__ void repack_big(const float* __restrict__ wr, const float* __restrict__ wi,
                           const float* __restrict__ br, const float* __restrict__ bi,
                           int which) {
    __half* dw = (which == 1) ? g_w1 : g_w2;
    float*  db = (which == 1) ? g_b1 : g_b2;
    int idx = blockIdx.x * blockDim.x + threadIdx.x;
    if (idx < CC) db[idx] = (idx < FF) ? br[idx] : bi[idx - FF];
    if (idx >= NCH*9*CC*CHUNK) return;
    int k    = idx % CHUNK;
    int cout = (idx / CHUNK) % CC;
    int t    = (idx / (CHUNK*CC)) % 9;
    int ci   = idx / (CHUNK*CC*9);
    int cin = ci*CHUNK + k;
    int fo = cout % FF, fi = cin % FF;
    const float* src = ((cout < FF) == (cin < FF)) ? wr : wi;
    float v = src[(fo*FF + fi)*9 + t];
    if (cout < FF && cin >= FF) v = -v;
    dw[swz_half_idx(idx)] = __float2half_rn(v);
}

__global__ void repack_small(const float* __restrict__ wr, const float* __restrict__ wi,
                             const float* __restrict__ br, const float* __restrict__ bi) {
    int idx = blockIdx.x * blockDim.x + threadIdx.x;
    if (idx < CC) g_b0[idx] = (idx < FF) ? br[idx] : bi[idx - FF];
    if (idx >= 2*9*CC) return;
    int cout = idx % CC;
    int t    = (idx / CC) % 9;
    int cin  = idx / (9*CC);
    int fo = cout % FF;
    const float* src = ((cout < FF) == (cin == 0)) ? wr : wi;
    float v = src[fo*9 + t];
    if (cout < FF && cin == 1) v = -v;
    g_w0[idx] = v;
}

// ---------------------------------------------------------------------------
// Layer 0: conv 2 -> 96, exact fp32; writes out + g_sig0 (half, interleaved)
// ---------------------------------------------------------------------------
__global__ __launch_bounds__(256)
void conv0_kernel(const float* __restrict__ xr, const float* __restrict__ xi,
                  float* __restrict__ out) {
    __shared__ float sw[2*9*CC];
    __shared__ float sb[CC];
    for (int i = threadIdx.x; i < 2*9*CC; i += 256) sw[i] = g_w0[i];
    if (threadIdx.x < CC) sb[threadIdx.x] = g_b0[threadIdx.x];
    __syncthreads();

    int pix = blockIdx.x * 256 + threadIdx.x;
    if (pix >= BB*HWW) return;
    int b = pix / HWW;
    int p = pix - b*HWW;
    int y = p / WW, x = p - y*WW;

    const float* x0 = xr + b*HWW;
    const float* x1 = xi + b*HWW;
    float in[18];
    #pragma unroll
    for (int dy = 0; dy < 3; dy++) {
        #pragma unroll
        for (int dx = 0; dx < 3; dx++) {
            int yy = y + dy - 1, xx = x + dx - 1;
            bool ok = (yy >= 0) && (yy < HH) && (xx >= 0) && (xx < WW);
            in[dy*3 + dx]     = ok ? x0[yy*WW + xx] : 0.0f;
            in[9 + dy*3 + dx] = ok ? x1[yy*WW + xx] : 0.0f;
        }
    }

    for (int ci = 0; ci < NCH; ci++) {
        uint32_t u[8];
        #pragma unroll
        for (int j2 = 0; j2 < 8; j2++) {
            float a2[2];
            #pragma unroll
            for (int s = 0; s < 2; s++) {
                int cout = ci*CHUNK + 2*j2 + s;
                float acc = sb[cout];
                #pragma unroll
                for (int t = 0; t < 18; t++)
                    acc = fmaf(in[t], sw[t*CC + cout], acc);
                int f = cout % FF, c2 = cout / FF;
                out[((b*FF + f)*HWW + p)*2 + c2] = acc;
                a2[s] = sigma_f(acc);
            }
            __half2 hh = __floats2half2_rn(a2[0], a2[1]);
            u[j2] = *reinterpret_cast<uint32_t*>(&hh);
        }
        uint4* dst = reinterpret_cast<uint4*>(
            g_sig0 + ((size_t)(b*NCH + ci)*HWW + p)*CHUNK);
        dst[0] = make_uint4(u[0], u[1], u[2], u[3]);
        dst[1] = make_uint4(u[4], u[5], u[6], u[7]);
    }
}

// ---------------------------------------------------------------------------
// Layers 1,2: persistent-weight fp16 m16n8k16 implicit GEMM (R10 champion).
// Grid = 148 CTAs x 256 thr (8 warps = 4M x 2N), 1 CTA/SM; CTA loops strips.
// Weights (166KB, swizzled) staged ONCE; A double-buffered via cp.async.
// Warp tile: m=32 px, n = {n0..n0+23} U {n0+48..n0+71} (real/imag pairs)
// -> epilogue writes float2 straight from fragments. Biases hoisted to regs.
// Row-wrap at x=0/319 wrong by construction -> fixup repairs.
// ---------------------------------------------------------------------------
template<int LAYER>
__global__ __launch_bounds__(256, 1)
void convT_kernel(float* __restrict__ out) {
    extern __shared__ __align__(256) char smem_raw[];
    uint32_t sb_base = smem_u32(smem_raw);
    uint32_t sa_base[2] = { sb_base + SA_OFF, sb_base + SA_OFF + ABUF_BYTES };
    __half* s_sig = reinterpret_cast<__half*>(smem_raw + SSIG_OFF);

    const __half* __restrict__ sig_in = (LAYER == 1) ? g_sig0 : g_sig1;
    const __half* __restrict__ wg     = (LAYER == 1) ? g_w1 : g_w2;
    const float*  __restrict__ bg     = (LAYER == 1) ? g_b1 : g_b2;

    int tid  = threadIdx.x;
    int warp = tid >> 5, lane = tid & 31;
    int m0 = (warp >> 1) * 32;
    int n0 = (warp & 1) * 24;
    int gid = lane >> 2, qid = lane & 3;
    int arow = lane & 15;
    uint32_t akoff = (uint32_t)(lane >> 4) * 16;

    // stage ALL weights once (swizzle pre-baked -> flat memcpy)
    {
        const uint4* srcw = reinterpret_cast<const uint4*>(wg);
        uint4* dstw = reinterpret_cast<uint4*>(smem_raw);
        for (int i = tid; i < SB_BYTES/16; i += 256) dstw[i] = srcw[i];
    }

    // hoisted biases for this warp's n-tile (once per kernel, not per job)
    float brl[3][2], bil[3][2];
    #pragma unroll
    for (int nt = 0; nt < 3; nt++) {
        int n = n0 + nt*8 + 2*qid;
        brl[nt][0] = __ldg(bg + n);      brl[nt][1] = __ldg(bg + n + 1);
        bil[nt][0] = __ldg(bg + n + 48); bil[nt][1] = __ldg(bg + n + 49);
    }
    __syncthreads();

    for (int job = blockIdx.x; job < NJOBS; job += gridDim.x) {
        int b     = job / NSTRIP;
        int strip = job - b*NSTRIP;
        int base  = strip * STRIP;
        const __half* plane0 = sig_in + (size_t)b*NCH*HWW*CHUNK;

        float acc[2][6][4];
        #pragma unroll
        for (int h = 0; h < 2; h++)
            #pragma unroll
            for (int nt = 0; nt < 6; nt++)
                #pragma unroll
                for (int r = 0; r < 4; r++) acc[h][nt][r] = 0.0f;

        // prefetch chunk 0
        {
            const __half* pc = plane0;
            for (int i = tid; i < 2*390; i += 256) {
                int blk = i >> 1, hi = i & 1;
                int dyr = blk / 130, px = blk - dyr*130;
                int fl  = base + (dyr - 1)*WW + px - 1;
                bool ok = (fl >= 0) && (fl < HWW);
                cp16(sa_base[0] + swz((uint32_t)(blk*32 + hi*16)),
                     pc + ((size_t)(ok ? fl : 0))*CHUNK + hi*8, ok);
            }
        }
        CP_COMMIT();

        for (int ci = 0; ci < NCH; ci++) {
            if (ci + 1 < NCH) {
                const __half* pc = plane0 + (size_t)(ci+1)*HWW*CHUNK;
                uint32_t ab = sa_base[(ci+1) & 1];
                for (int i = tid; i < 2*390; i += 256) {
                    int blk = i >> 1, hi = i & 1;
                    int dyr = blk / 130, px = blk - dyr*130;
                    int fl  = base + (dyr - 1)*WW + px - 1;
                    bool ok = (fl >= 0) && (fl < HWW);
                    cp16(ab + swz((uint32_t)(blk*32 + hi*16)),
                         pc + ((size_t)(ok ? fl : 0))*CHUNK + hi*8, ok);
                }
                CP_COMMIT();
                CP_WAIT1();
            } else {
                CP_WAIT0();
            }
            __syncthreads();

            uint32_t sa = sa_base[ci & 1];
            uint32_t cioff = (uint32_t)ci * (9*CC*32);
            #pragma unroll
            for (int tap = 0; tap < 9; tap++) {
                int dy = tap / 3, dx = tap - dy*3;
                uint32_t boff = cioff + (uint32_t)tap * (CC*32);
                uint32_t bf[6][2];
                #pragma unroll
                for (int nt = 0; nt < 6; nt++) {
                    int nrow = ((nt < 3) ? (n0 + nt*8) : (48 + n0 + (nt-3)*8)) + gid;
                    uint32_t o = boff + (uint32_t)nrow*32 + (uint32_t)qid*4;
                    bf[nt][0] = lds32(sb_base + swz(o));
                    bf[nt][1] = lds32(sb_base + swz(o + 16));
                }
                #pragma unroll
                for (int h = 0; h < 2; h++) {
                    int p = dy*130 + dx + m0 + h*16 + arow;
                    uint32_t a[4];
                    ldmA(a, sa + swz((uint32_t)p*32 + akoff));
                    #pragma unroll
                    for (int nt = 0; nt < 6; nt++)
                        mma_f16(acc[h][nt], a, bf[nt]);
                }
            }
            __syncthreads();
        }

        // --- epilogue: direct float2 stores from fragments ---
        float2* ob = reinterpret_cast<float2*>(out)
                   + (size_t)(LAYER*BB + b)*FF*HWW + base;
        #pragma unroll
        for (int h = 0; h < 2; h++) {
            int m = m0 + h*16 + gid;
            #pragma unroll
            for (int nt = 0; nt < 3; nt++) {
                int n = n0 + nt*8 + 2*qid;
                float re0 = acc[h][nt][0] + brl[nt][0], re1 = acc[h][nt][1] + brl[nt][1];
                float re2 = acc[h][nt][2] + brl[nt][0], re3 = acc[h][nt][3] + brl[nt][1];
                float im0 = acc[h][nt+3][0] + bil[nt][0], im1 = acc[h][nt+3][1] + bil[nt][1];
                float im2 = acc[h][nt+3][2] + bil[nt][0], im3 = acc[h][nt+3][3] + bil[nt][1];
                ob[(size_t)n*HWW + m]         = make_float2(re0, im0);
                ob[(size_t)(n+1)*HWW + m]     = make_float2(re1, im1);
                ob[(size_t)n*HWW + m + 8]     = make_float2(re2, im2);
                ob[(size_t)(n+1)*HWW + m + 8] = make_float2(re3, im3);
                if (LAYER == 1) {
                    __half2* sg;
                    sg = reinterpret_cast<__half2*>(s_sig + m*CC + n);
                    *sg = __floats2half2_rn(sigma_f(re0), sigma_f(re1));
                    sg = reinterpret_cast<__half2*>(s_sig + m*CC + n + 48);
                    *sg = __floats2half2_rn(sigma_f(im0), sigma_f(im1));
                    sg = reinterpret_cast<__half2*>(s_sig + (m+8)*CC + n);
                    *sg = __floats2half2_rn(sigma_f(re2), sigma_f(re3));
                    sg = reinterpret_cast<__half2*>(s_sig + (m+8)*CC + n + 48);
                    *sg = __floats2half2_rn(sigma_f(im2), sigma_f(im3));
                }
            }
        }
        if (LAYER == 1) {
            __syncthreads();   // s_sig complete across warps
            for (int i = tid; i < NCH*STRIP; i += 256) {
                int ci = i >> 7;
                int px = i & (STRIP-1);
                const uint4* srcv = reinterpret_cast<const uint4*>(
                    s_sig + px*CC + ci*CHUNK);
                uint4* dst = reinterpret_cast<uint4*>(
                    g_sig1 + ((size_t)(b*NCH + ci)*HWW + base + px)*CHUNK);
                dst[0] = srcv[0];
                dst[1] = srcv[1];
            }
            __syncthreads();   // s_sig aliases A buffers: done before next prefetch
        }
    }
}

// ---------------------------------------------------------------------------
// Border fixup: recompute columns x=0 and x=319 for layer L (x-wrap repair).
// ---------------------------------------------------------------------------
template<int LAYER>
__global__ __launch_bounds__(96)
void fixup_kernel(float* __restrict__ out) {
    const __half* __restrict__ sig_in = (LAYER == 1) ? g_sig0 : g_sig1;
    const __half* __restrict__ wg     = (LAYER == 1) ? g_w1 : g_w2;
    const float*  __restrict__ bg     = (LAYER == 1) ? g_b1 : g_b2;

    int blk  = blockIdx.x;
    int side = blk & 1;
    int y    = (blk >> 1) % HH;
    int b    = (blk >> 1) / HH;
    int x    = side ? (WW-1) : 0;
    int xs   = side ? (WW-2) : 0;
    int cout = threadIdx.x;

    __shared__ float s_act[3][2][CC];
    for (int i = cout; i < 3*2*CC; i += 96) {
        int c   = i % CC;
        int dxl = (i / CC) % 2;
        int dy  = i / (2*CC);
        int yy  = y + dy - 1;
        float v = 0.0f;
        if (yy >= 0 && yy < HH)
            v = __half2float(sig_in[((size_t)(b*NCH + c/CHUNK)*HWW
                                     + yy*WW + xs + dxl)*CHUNK + (c % CHUNK)]);
        s_act[dy][dxl][c] = v;
    }
    __syncthreads();

    float acc = bg[cout];
    #pragma unroll
    for (int dy = 0; dy < 3; dy++)
        #pragma unroll
        for (int dx = 0; dx < 3; dx++) {
            int xx = x + dx - 1;
            if (xx < 0 || xx >= WW) continue;
            int dxl = xx - xs;
            for (int c = 0; c < CC; c++) {
                int hidx = (((c/CHUNK)*9 + dy*3 + dx)*CC + cout)*CHUNK + (c % CHUNK);
                float w = __half2float(wg[swz_half_idx(hidx)]);
                acc = fmaf(w, s_act[dy][dxl][c], acc);
            }
        }

    int p = y*WW + x;
    if (LAYER == 1)
        g_sig1[((size_t)(b*NCH + cout/CHUNK)*HWW + p)*CHUNK + (cout % CHUNK)]
            = __float2half_rn(sigma_f(acc));
    int f = cout % FF, c2 = cout / FF;
    out[(((size_t)(LAYER*BB + b)*FF + f)*HWW + p)*2 + c2] = acc;
}

extern "C" void kernel_launch(void* const* d_in, const int* in_sizes, int n_in,
                              void* d_out, int out_size) {
    const float* x_real = (const float*)d_in[0];
    const float* x_imag = (const float*)d_in[1];
    const float* w0r = (const float*)d_in[2];
    const float* w0i = (const float*)d_in[3];
    const float* b0r = (const float*)d_in[4];
    const float* b0i = (const float*)d_in[5];
    const float* w1r = (const float*)d_in[6];
    const float* w1i = (const float*)d_in[7];
    const float* b1r = (const float*)d_in[8];
    const float* b1i = (const float*)d_in[9];
    const float* w2r = (const float*)d_in[10];
    const float* w2i = (const float*)d_in[11];
    const float* b2r = (const float*)d_in[12];
    const float* b2i = (const float*)d_in[13];
    float* out = (float*)d_out;

    static bool attr_set = false;
    if (!attr_set) {
        cudaFuncSetAttribute(convT_kernel<1>, cudaFuncAttributeMaxDynamicSharedMemorySize, SMEM_BYTES);
        cudaFuncSetAttribute(convT_kernel<2>, cudaFuncAttributeMaxDynamicSharedMemorySize, SMEM_BYTES);
        attr_set = true;
    }

    repack_small<<<(2*9*CC + 255)/256, 256>>>(w0r, w0i, b0r, b0i);
    repack_big<<<(NCH*9*CC*CHUNK + 255)/256, 256>>>(w1r, w1i, b1r, b1i, 1);
    repack_big<<<(NCH*9*CC*CHUNK + 255)/256, 256>>>(w2r, w2i, b2r, b2i, 2);

    conv0_kernel<<<(BB*HWW + 255)/256, 256>>>(x_real, x_imag, out);

    convT_kernel<1><<<NCTAS, 256, SMEM_BYTES>>>(out);
    fixup_kernel<1><<<BB*HH*2, 96>>>(out);
    convT_kernel<2><<<NCTAS, 256, SMEM_BYTES>>>(out);
    fixup_kernel<2><<<BB*HH*2, 96>>>(out);
}

// round 15
// speedup vs baseline: 1.0917x; 1.0104x over previous
#include <cuda_runtime.h>
#include <cuda_fp16.h>
#include <cstdint>

#define BB 2
#define FF 48
#define CC 96
#define HH 320
#define WW 320
#define HWW (HH*WW)

#define STRIP 128
#define NSTRIP (HWW/STRIP)   // 800
#define NJOBS (NSTRIP*BB)    // 1600
#define CHUNK 16
#define NCH (CC/CHUNK)       // 6
#define NCTAS 148

// smem: B (all weights) at 0, then two A buffers; s_sig aliases A buffers.
#define SB_BYTES (NCH*9*CC*32)          // 165888 (rows of 32B, XOR-swizzled)
#define ABUF_BYTES 12800                // 390 rows * 32B = 12480, padded to 256B mult
#define SA_OFF SB_BYTES                 // 165888 (256B aligned)
#define SMEM_BYTES (SB_BYTES + 2*ABUF_BYTES)   // 191488
#define SSIG_OFF SB_BYTES               // 24576B needed <= 25600 available

#define WELEMS (NCH*9*CC*CHUNK)         // 82944 weight elements per layer

// sigma'd activations, fp16, pixel-interleaved by 16-ch chunk: [b][ci][pix][k16]
__device__ __align__(16) __half g_sig0[(size_t)BB*NCH*HWW*CHUNK];
__device__ __align__(16) __half g_sig1[(size_t)BB*NCH*HWW*CHUNK];
// weights: fp16, [ci][tap][cout96][k16] with 16B XOR swizzle pre-baked
__device__ float  g_w0[2*9*CC];
__device__ __align__(16) __half g_w1[WELEMS];
__device__ __align__(16) __half g_w2[WELEMS];
__device__ float g_b0[CC];
__device__ float g_b1[CC];
__device__ float g_b2[CC];

__device__ __forceinline__ float sigma_f(float u) {
    float quad = fmaf(u, fmaf(u, 250.0f, 0.5f), 0.00025f);
    return (fabsf(u) > 0.001f) ? fmaxf(u, 0.0f) : quad;
}

// 16B XOR swizzle on byte offsets within a 256B-aligned region:
// rows (32B) with bit2 set swap their two 16B halves -> conflict-free LDS/ldmatrix
__device__ __forceinline__ uint32_t swz(uint32_t off) {
    return off ^ ((off & 128u) >> 3);
}
__device__ __host__ __forceinline__ int swz_half_idx(int h) {   // same transform on half index
    return h ^ ((h >> 3) & 8);
}

__device__ __forceinline__ uint32_t smem_u32(const void* p) {
    return (uint32_t)__cvta_generic_to_shared(p);
}
__device__ __forceinline__ uint32_t lds32(uint32_t addr) {
    uint32_t v; asm volatile("ld.shared.b32 %0, [%1];" : "=r"(v) : "r"(addr)); return v;
}
__device__ __forceinline__ void ldmA(uint32_t* r, uint32_t addr) {
    asm volatile("ldmatrix.sync.aligned.m8n8.x4.shared.b16 {%0,%1,%2,%3}, [%4];"
        : "=r"(r[0]), "=r"(r[1]), "=r"(r[2]), "=r"(r[3]) : "r"(addr));
}
__device__ __forceinline__ void mma_f16(float* d, const uint32_t* a, const uint32_t* b) {
    asm("mma.sync.aligned.m16n8k16.row.col.f32.f16.f16.f32 "
        "{%0,%1,%2,%3}, {%4,%5,%6,%7}, {%8,%9}, {%0,%1,%2,%3};"
        : "+f"(d[0]), "+f"(d[1]), "+f"(d[2]), "+f"(d[3])
        : "r"(a[0]), "r"(a[1]), "r"(a[2]), "r"(a[3]), "r"(b[0]), "r"(b[1]));
}
__device__ __forceinline__ void cp16(uint32_t dst, const void* src, bool valid) {
    int sz = valid ? 16 : 0;
    asm volatile("cp.async.cg.shared.global [%0], [%1], 16, %2;"
                 :: "r"(dst), "l"(src), "r"(sz) : "memory");
}
#define CP_COMMIT() asm volatile("cp.async.commit_group;" ::: "memory")
#define CP_WAIT1()  asm volatile("cp.async.wait_group 1;" ::: "memory")
#define CP_WAIT0()  asm volatile("cp.async.wait_group 0;" ::: "memory")

// ---------------------------------------------------------------------------
// Merged weight repack: one launch does w1, w2 (fp16 swizzled chunk images),
// w0 (fp32), and all three bias vectors. Identical per-element math to the
// previous three kernels.
// ---------------------------------------------------------------------------
__device__ __forceinline__ void repack_one_big(
    __half* dw, const float* wr, const float* wi, int e) {
    int k    = e % CHUNK;
    int cout = (e / CHUNK) % CC;
    int t    = (e / (CHUNK*CC)) % 9;
    int ci   = e / (CHUNK*CC*9);
    int cin = ci*CHUNK + k;
    int fo = cout % FF, fi = cin % FF;
    const float* src = ((cout < FF) == (cin < FF)) ? wr : wi;
    float v = src[(fo*FF + fi)*9 + t];
    if (cout < FF && cin >= FF) v = -v;
    dw[swz_half_idx(e)] = __float2half_rn(v);
}

__global__ void repack_all(
    const float* __restrict__ w0r, const float* __restrict__ w0i,
    const float* __restrict__ b0r, const float* __restrict__ b0i,
    const float* __restrict__ w1r, const float* __restrict__ w1i,
    const float* __restrict__ b1r, const float* __restrict__ b1i,
    const float* __restrict__ w2r, const float* __restrict__ w2i,
    const float* __restrict__ b2r, const float* __restrict__ b2i) {
    int idx = blockIdx.x * blockDim.x + threadIdx.x;
    if (idx < CC) {
        g_b0[idx] = (idx < FF) ? b0r[idx] : b0i[idx - FF];
        g_b1[idx] = (idx < FF) ? b1r[idx] : b1i[idx - FF];
        g_b2[idx] = (idx < FF) ? b2r[idx] : b2i[idx - FF];
    }
    if (idx < WELEMS) {
        repack_one_big(g_w1, w1r, w1i, idx);
        return;
    }
    int e = idx - WELEMS;
    if (e < WELEMS) {
        repack_one_big(g_w2, w2r, w2i, e);
        return;
    }
    e -= WELEMS;
    if (e < 2*9*CC) {
        int cout = e % CC;
        int t    = (e / CC) % 9;
        int cin  = e / (9*CC);
        int fo = cout % FF;
        const float* src = ((cout < FF) == (cin == 0)) ? w0r : w0i;
        float v = src[fo*9 + t];
        if (cout < FF && cin == 1) v = -v;
        g_w0[e] = v;
    }
}
#define REPACK_TOTAL (2*WELEMS + 2*9*CC)

// ---------------------------------------------------------------------------
// Layer 0: conv 2 -> 96, exact fp32; writes out + g_sig0 (half, interleaved)
// ---------------------------------------------------------------------------
__global__ __launch_bounds__(256)
void conv0_kernel(const float* __restrict__ xr, const float* __restrict__ xi,
                  float* __restrict__ out) {
    __shared__ float sw[2*9*CC];
    __shared__ float sb[CC];
    for (int i = threadIdx.x; i < 2*9*CC; i += 256) sw[i] = g_w0[i];
    if (threadIdx.x < CC) sb[threadIdx.x] = g_b0[threadIdx.x];
    __syncthreads();

    int pix = blockIdx.x * 256 + threadIdx.x;
    if (pix >= BB*HWW) return;
    int b = pix / HWW;
    int p = pix - b*HWW;
    int y = p / WW, x = p - y*WW;

    const float* x0 = xr + b*HWW;
    const float* x1 = xi + b*HWW;
    float in[18];
    #pragma unroll
    for (int dy = 0; dy < 3; dy++) {
        #pragma unroll
        for (int dx = 0; dx < 3; dx++) {
            int yy = y + dy - 1, xx = x + dx - 1;
            bool ok = (yy >= 0) && (yy < HH) && (xx >= 0) && (xx < WW);
            in[dy*3 + dx]     = ok ? x0[yy*WW + xx] : 0.0f;
            in[9 + dy*3 + dx] = ok ? x1[yy*WW + xx] : 0.0f;
        }
    }

    for (int ci = 0; ci < NCH; ci++) {
        uint32_t u[8];
        #pragma unroll
        for (int j2 = 0; j2 < 8; j2++) {
            float a2[2];
            #pragma unroll
            for (int s = 0; s < 2; s++) {
                int cout = ci*CHUNK + 2*j2 + s;
                float acc = sb[cout];
                #pragma unroll
                for (int t = 0; t < 18; t++)
                    acc = fmaf(in[t], sw[t*CC + cout], acc);
                int f = cout % FF, c2 = cout / FF;
                out[((b*FF + f)*HWW + p)*2 + c2] = acc;
                a2[s] = sigma_f(acc);
            }
            __half2 hh = __floats2half2_rn(a2[0], a2[1]);
            u[j2] = *reinterpret_cast<uint32_t*>(&hh);
        }
        uint4* dst = reinterpret_cast<uint4*>(
            g_sig0 + ((size_t)(b*NCH + ci)*HWW + p)*CHUNK);
        dst[0] = make_uint4(u[0], u[1], u[2], u[3]);
        dst[1] = make_uint4(u[4], u[5], u[6], u[7]);
    }
}

// ---------------------------------------------------------------------------
// Layers 1,2: persistent-weight fp16 m16n8k16 implicit GEMM (R14 champion,
// byte-identical). Grid = 148 CTAs x 256 thr (8 warps = 4M x 2N), 1 CTA/SM.
// Weights (166KB, swizzled) staged ONCE; A double-buffered via cp.async.
// Warp tile: m=32 px, n = {n0..n0+23} U {n0+48..n0+71} (real/imag pairs)
// -> epilogue writes float2 straight from fragments. Biases hoisted to regs.
// Row-wrap at x=0/319 wrong by construction -> fixup repairs.
// ---------------------------------------------------------------------------
template<int LAYER>
__global__ __launch_bounds__(256, 1)
void convT_kernel(float* __restrict__ out) {
    extern __shared__ __align__(256) char smem_raw[];
    uint32_t sb_base = smem_u32(smem_raw);
    uint32_t sa_base[2] = { sb_base + SA_OFF, sb_base + SA_OFF + ABUF_BYTES };
    __half* s_sig = reinterpret_cast<__half*>(smem_raw + SSIG_OFF);

    const __half* __restrict__ sig_in = (LAYER == 1) ? g_sig0 : g_sig1;
    const __half* __restrict__ wg     = (LAYER == 1) ? g_w1 : g_w2;
    const float*  __restrict__ bg     = (LAYER == 1) ? g_b1 : g_b2;

    int tid  = threadIdx.x;
    int warp = tid >> 5, lane = tid & 31;
    int m0 = (warp >> 1) * 32;
    int n0 = (warp & 1) * 24;
    int gid = lane >> 2, qid = lane & 3;
    int arow = lane & 15;
    uint32_t akoff = (uint32_t)(lane >> 4) * 16;

    // stage ALL weights once (swizzle pre-baked -> flat memcpy)
    {
        const uint4* srcw = reinterpret_cast<const uint4*>(wg);
        uint4* dstw = reinterpret_cast<uint4*>(smem_raw);
        for (int i = tid; i < SB_BYTES/16; i += 256) dstw[i] = srcw[i];
    }

    // hoisted biases for this warp's n-tile (once per kernel, not per job)
    float brl[3][2], bil[3][2];
    #pragma unroll
    for (int nt = 0; nt < 3; nt++) {
        int n = n0 + nt*8 + 2*qid;
        brl[nt][0] = __ldg(bg + n);      brl[nt][1] = __ldg(bg + n + 1);
        bil[nt][0] = __ldg(bg + n + 48); bil[nt][1] = __ldg(bg + n + 49);
    }
    __syncthreads();

    for (int job = blockIdx.x; job < NJOBS; job += gridDim.x) {
        int b     = job / NSTRIP;
        int strip = job - b*NSTRIP;
        int base  = strip * STRIP;
        const __half* plane0 = sig_in + (size_t)b*NCH*HWW*CHUNK;

        float acc[2][6][4];
        #pragma unroll
        for (int h = 0; h < 2; h++)
            #pragma unroll
            for (int nt = 0; nt < 6; nt++)
                #pragma unroll
                for (int r = 0; r < 4; r++) acc[h][nt][r] = 0.0f;

        // prefetch chunk 0
        {
            const __half* pc = plane0;
            for (int i = tid; i < 2*390; i += 256) {
                int blk = i >> 1, hi = i & 1;
                int dyr = blk / 130, px = blk - dyr*130;
                int fl  = base + (dyr - 1)*WW + px - 1;
                bool ok = (fl >= 0) && (fl < HWW);
                cp16(sa_base[0] + swz((uint32_t)(blk*32 + hi*16)),
                     pc + ((size_t)(ok ? fl : 0))*CHUNK + hi*8, ok);
            }
        }
        CP_COMMIT();

        for (int ci = 0; ci < NCH; ci++) {
            if (ci + 1 < NCH) {
                const __half* pc = plane0 + (size_t)(ci+1)*HWW*CHUNK;
                uint32_t ab = sa_base[(ci+1) & 1];
                for (int i = tid; i < 2*390; i += 256) {
                    int blk = i >> 1, hi = i & 1;
                    int dyr = blk / 130, px = blk - dyr*130;
                    int fl  = base + (dyr - 1)*WW + px - 1;
                    bool ok = (fl >= 0) && (fl < HWW);
                    cp16(ab + swz((uint32_t)(blk*32 + hi*16)),
                         pc + ((size_t)(ok ? fl : 0))*CHUNK + hi*8, ok);
                }
                CP_COMMIT();
                CP_WAIT1();
            } else {
                CP_WAIT0();
            }
            __syncthreads();

            uint32_t sa = sa_base[ci & 1];
            uint32_t cioff = (uint32_t)ci * (9*CC*32);
            #pragma unroll
            for (int tap = 0; tap < 9; tap++) {
                int dy = tap / 3, dx = tap - dy*3;
                uint32_t boff = cioff + (uint32_t)tap * (CC*32);
                uint32_t bf[6][2];
                #pragma unroll
                for (int nt = 0; nt < 6; nt++) {
                    int nrow = ((nt < 3) ? (n0 + nt*8) : (48 + n0 + (nt-3)*8)) + gid;
                    uint32_t o = boff + (uint32_t)nrow*32 + (uint32_t)qid*4;
                    bf[nt][0] = lds32(sb_base + swz(o));
                    bf[nt][1] = lds32(sb_base + swz(o + 16));
                }
                #pragma unroll
                for (int h = 0; h < 2; h++) {
                    int p = dy*130 + dx + m0 + h*16 + arow;
                    uint32_t a[4];
                    ldmA(a, sa + swz((uint32_t)p*32 + akoff));
                    #pragma unroll
                    for (int nt = 0; nt < 6; nt++)
                        mma_f16(acc[h][nt], a, bf[nt]);
                }
            }
            __syncthreads();
        }

        // --- epilogue: direct float2 stores from fragments ---
        float2* ob = reinterpret_cast<float2*>(out)
                   + (size_t)(LAYER*BB + b)*FF*HWW + base;
        #pragma unroll
        for (int h = 0; h < 2; h++) {
            int m = m0 + h*16 + gid;
            #pragma unroll
            for (int nt = 0; nt < 3; nt++) {
                int n = n0 + nt*8 + 2*qid;
                float re0 = acc[h][nt][0] + brl[nt][0], re1 = acc[h][nt][1] + brl[nt][1];
                float re2 = acc[h][nt][2] + brl[nt][0], re3 = acc[h][nt][3] + brl[nt][1];
                float im0 = acc[h][nt+3][0] + bil[nt][0], im1 = acc[h][nt+3][1] + bil[nt][1];
                float im2 = acc[h][nt+3][2] + bil[nt][0], im3 = acc[h][nt+3][3] + bil[nt][1];
                ob[(size_t)n*HWW + m]         = make_float2(re0, im0);
                ob[(size_t)(n+1)*HWW + m]     = make_float2(re1, im1);
                ob[(size_t)n*HWW + m + 8]     = make_float2(re2, im2);
                ob[(size_t)(n+1)*HWW + m + 8] = make_float2(re3, im3);
                if (LAYER == 1) {
                    __half2* sg;
                    sg = reinterpret_cast<__half2*>(s_sig + m*CC + n);
                    *sg = __floats2half2_rn(sigma_f(re0), sigma_f(re1));
                    sg = reinterpret_cast<__half2*>(s_sig + m*CC + n + 48);
                    *sg = __floats2half2_rn(sigma_f(im0), sigma_f(im1));
                    sg = reinterpret_cast<__half2*>(s_sig + (m+8)*CC + n);
                    *sg = __floats2half2_rn(sigma_f(re2), sigma_f(re3));
                    sg = reinterpret_cast<__half2*>(s_sig + (m+8)*CC + n + 48);
                    *sg = __floats2half2_rn(sigma_f(im2), sigma_f(im3));
                }
            }
        }
        if (LAYER == 1) {
            __syncthreads();   // s_sig complete across warps
            for (int i = tid; i < NCH*STRIP; i += 256) {
                int ci = i >> 7;
                int px = i & (STRIP-1);
                const uint4* srcv = reinterpret_cast<const uint4*>(
                    s_sig + px*CC + ci*CHUNK);
                uint4* dst = reinterpret_cast<uint4*>(
                    g_sig1 + ((size_t)(b*NCH + ci)*HWW + base + px)*CHUNK);
                dst[0] = srcv[0];
                dst[1] = srcv[1];
            }
            __syncthreads();   // s_sig aliases A buffers: done before next prefetch
        }
    }
}

// ---------------------------------------------------------------------------
// Border fixup: recompute columns x=0 and x=319 for layer L (x-wrap repair).
// ---------------------------------------------------------------------------
template<int LAYER>
__global__ __launch_bounds__(96)
void fixup_kernel(float* __restrict__ out) {
    const __half* __restrict__ sig_in = (LAYER == 1) ? g_sig0 : g_sig1;
    const __half* __restrict__ wg     = (LAYER == 1) ? g_w1 : g_w2;
    const float*  __restrict__ bg     = (LAYER == 1) ? g_b1 : g_b2;

    int blk  = blockIdx.x;
    int side = blk & 1;
    int y    = (blk >> 1) % HH;
    int b    = (blk >> 1) / HH;
    int x    = side ? (WW-1) : 0;
    int xs   = side ? (WW-2) : 0;
    int cout = threadIdx.x;

    __shared__ float s_act[3][2][CC];
    for (int i = cout; i < 3*2*CC; i += 96) {
        int c   = i % CC;
        int dxl = (i / CC) % 2;
        int dy  = i / (2*CC);
        int yy  = y + dy - 1;
        float v = 0.0f;
        if (yy >= 0 && yy < HH)
            v = __half2float(sig_in[((size_t)(b*NCH + c/CHUNK)*HWW
                                     + yy*WW + xs + dxl)*CHUNK + (c % CHUNK)]);
        s_act[dy][dxl][c] = v;
    }
    __syncthreads();

    float acc = bg[cout];
    #pragma unroll
    for (int dy = 0; dy < 3; dy++)
        #pragma unroll
        for (int dx = 0; dx < 3; dx++) {
            int xx = x + dx - 1;
            if (xx < 0 || xx >= WW) continue;
            int dxl = xx - xs;
            for (int c = 0; c < CC; c++) {
                int hidx = (((c/CHUNK)*9 + dy*3 + dx)*CC + cout)*CHUNK + (c % CHUNK);
                float w = __half2float(wg[swz_half_idx(hidx)]);
                acc = fmaf(w, s_act[dy][dxl][c], acc);
            }
        }

    int p = y*WW + x;
    if (LAYER == 1)
        g_sig1[((size_t)(b*NCH + cout/CHUNK)*HWW + p)*CHUNK + (cout % CHUNK)]
            = __float2half_rn(sigma_f(acc));
    int f = cout % FF, c2 = cout / FF;
    out[(((size_t)(LAYER*BB + b)*FF + f)*HWW + p)*2 + c2] = acc;
}

extern "C" void kernel_launch(void* const* d_in, const int* in_sizes, int n_in,
                              void* d_out, int out_size) {
    const float* x_real = (const float*)d_in[0];
    const float* x_imag = (const float*)d_in[1];
    const float* w0r = (const float*)d_in[2];
    const float* w0i = (const float*)d_in[3];
    const float* b0r = (const float*)d_in[4];
    const float* b0i = (const float*)d_in[5];
    const float* w1r = (const float*)d_in[6];
    const float* w1i = (const float*)d_in[7];
    const float* b1r = (const float*)d_in[8];
    const float* b1i = (const float*)d_in[9];
    const float* w2r = (const float*)d_in[10];
    const float* w2i = (const float*)d_in[11];
    const float* b2r = (const float*)d_in[12];
    const float* b2i = (const float*)d_in[13];
    float* out = (float*)d_out;

    static bool attr_set = false;
    if (!attr_set) {
        cudaFuncSetAttribute(convT_kernel<1>, cudaFuncAttributeMaxDynamicSharedMemorySize, SMEM_BYTES);
        cudaFuncSetAttribute(convT_kernel<2>, cudaFuncAttributeMaxDynamicSharedMemorySize, SMEM_BYTES);
        attr_set = true;
    }

    repack_all<<<(REPACK_TOTAL + 255)/256, 256>>>(
        w0r, w0i, b0r, b0i, w1r, w1i, b1r, b1i, w2r, w2i, b2r, b2i);

    conv0_kernel<<<(BB*HWW + 255)/256, 256>>>(x_real, x_imag, out);

    convT_kernel<1><<<NCTAS, 256, SMEM_BYTES>>>(out);
    fixup_kernel<1><<<BB*HH*2, 96>>>(out);
    convT_kernel<2><<<NCTAS, 256, SMEM_BYTES>>>(out);
    fixup_kernel<2><<<BB*HH*2, 96>>>(out);
}

// round 17
// speedup vs baseline: 1.2815x; 1.1738x over previous
#include <cuda_runtime.h>
#include <cuda_fp16.h>
#include <cstdint>

#define BB 2
#define FF 48
#define CC 96
#define HH 320
#define WW 320
#define HWW (HH*WW)

#define STRIP 128
#define NSTRIP (HWW/STRIP)   // 800
#define NJOBS (NSTRIP*BB)    // 1600
#define CHUNK 16
#define NCH (CC/CHUNK)       // 6
#define NCTAS 148

// smem: B (all weights) at 0 | two A buffers | fix scratch; s_sig aliases A bufs.
#define SB_BYTES (NCH*9*CC*32)          // 165888 (rows of 32B, XOR-swizzled)
#define ABUF_BYTES 12800                // 390 rows * 32B, padded
#define SA_OFF SB_BYTES
#define SSIG_OFF SB_BYTES               // 24576B needed <= 25600 available
#define FIX_OFF (SB_BYTES + 2*ABUF_BYTES)   // 191488
#define SMEM_BYTES (FIX_OFF + 2048)     // 193536: s_fact 1152B + s_corr 768B

#define WELEMS (NCH*9*CC*CHUNK)         // 82944 weight elements per layer

// sigma'd activations, fp16, pixel-interleaved by 16-ch chunk: [b][ci][pix][k16]
__device__ __align__(16) __half g_sig0[(size_t)BB*NCH*HWW*CHUNK];
__device__ __align__(16) __half g_sig1[(size_t)BB*NCH*HWW*CHUNK];
// weights: fp16, [ci][tap][cout96][k16] with 16B XOR swizzle pre-baked
__device__ float  g_w0[2*9*CC];
__device__ __align__(16) __half g_w1[WELEMS];
__device__ __align__(16) __half g_w2[WELEMS];
__device__ float g_b0[CC];
__device__ float g_b1[CC];
__device__ float g_b2[CC];

__device__ __forceinline__ float sigma_f(float u) {
    float quad = fmaf(u, fmaf(u, 250.0f, 0.5f), 0.00025f);
    return (fabsf(u) > 0.001f) ? fmaxf(u, 0.0f) : quad;
}

__device__ __forceinline__ uint32_t swz(uint32_t off) {
    return off ^ ((off & 128u) >> 3);
}
__device__ __host__ __forceinline__ int swz_half_idx(int h) {
    return h ^ ((h >> 3) & 8);
}

__device__ __forceinline__ uint32_t smem_u32(const void* p) {
    return (uint32_t)__cvta_generic_to_shared(p);
}
__device__ __forceinline__ uint32_t lds32(uint32_t addr) {
    uint32_t v; asm volatile("ld.shared.b32 %0, [%1];" : "=r"(v) : "r"(addr)); return v;
}
__device__ __forceinline__ void ldmA(uint32_t* r, uint32_t addr) {
    asm volatile("ldmatrix.sync.aligned.m8n8.x4.shared.b16 {%0,%1,%2,%3}, [%4];"
        : "=r"(r[0]), "=r"(r[1]), "=r"(r[2]), "=r"(r[3]) : "r"(addr));
}
__device__ __forceinline__ void mma_f16(float* d, const uint32_t* a, const uint32_t* b) {
    asm("mma.sync.aligned.m16n8k16.row.col.f32.f16.f16.f32 "
        "{%0,%1,%2,%3}, {%4,%5,%6,%7}, {%8,%9}, {%0,%1,%2,%3};"
        : "+f"(d[0]), "+f"(d[1]), "+f"(d[2]), "+f"(d[3])
        : "r"(a[0]), "r"(a[1]), "r"(a[2]), "r"(a[3]), "r"(b[0]), "r"(b[1]));
}
__device__ __forceinline__ void cp16(uint32_t dst, const void* src, bool valid) {
    int sz = valid ? 16 : 0;
    asm volatile("cp.async.cg.shared.global [%0], [%1], 16, %2;"
                 :: "r"(dst), "l"(src), "r"(sz) : "memory");
}
#define CP_COMMIT() asm volatile("cp.async.commit_group;" ::: "memory")
#define CP_WAIT1()  asm volatile("cp.async.wait_group 1;" ::: "memory")
#define CP_WAIT0()  asm volatile("cp.async.wait_group 0;" ::: "memory")

// ---------------------------------------------------------------------------
// Merged weight repack (one launch: w1, w2, w0, all biases)
// ---------------------------------------------------------------------------
__device__ __forceinline__ void repack_one_big(
    __half* dw, const float* wr, const float* wi, int e) {
    int k    = e % CHUNK;
    int cout = (e / CHUNK) % CC;
    int t    = (e / (CHUNK*CC)) % 9;
    int ci   = e / (CHUNK*CC*9);
    int cin = ci*CHUNK + k;
    int fo = cout % FF, fi = cin % FF;
    const float* src = ((cout < FF) == (cin < FF)) ? wr : wi;
    float v = src[(fo*FF + fi)*9 + t];
    if (cout < FF && cin >= FF) v = -v;
    dw[swz_half_idx(e)] = __float2half_rn(v);
}

__global__ void repack_all(
    const float* __restrict__ w0r, const float* __restrict__ w0i,
    const float* __restrict__ b0r, const float* __restrict__ b0i,
    const float* __restrict__ w1r, const float* __restrict__ w1i,
    const float* __restrict__ b1r, const float* __restrict__ b1i,
    const float* __restrict__ w2r, const float* __restrict__ w2i,
    const float* __restrict__ b2r, const float* __restrict__ b2i) {
    int idx = blockIdx.x * blockDim.x + threadIdx.x;
    if (idx < CC) {
        g_b0[idx] = (idx < FF) ? b0r[idx] : b0i[idx - FF];
        g_b1[idx] = (idx < FF) ? b1r[idx] : b1i[idx - FF];
        g_b2[idx] = (idx < FF) ? b2r[idx] : b2i[idx - FF];
    }
    if (idx < WELEMS) { repack_one_big(g_w1, w1r, w1i, idx); return; }
    int e = idx - WELEMS;
    if (e < WELEMS) { repack_one_big(g_w2, w2r, w2i, e); return; }
    e -= WELEMS;
    if (e < 2*9*CC) {
        int cout = e % CC;
        int t    = (e / CC) % 9;
        int cin  = e / (9*CC);
        int fo = cout % FF;
        const float* src = ((cout < FF) == (cin == 0)) ? w0r : w0i;
        float v = src[fo*9 + t];
        if (cout < FF && cin == 1) v = -v;
        g_w0[e] = v;
    }
}
#define REPACK_TOTAL (2*WELEMS + 2*9*CC)

// ---------------------------------------------------------------------------
// Layer 0: conv 2 -> 96, exact fp32; writes out + g_sig0 (half, interleaved)
// ---------------------------------------------------------------------------
__global__ __launch_bounds__(256)
void conv0_kernel(const float* __restrict__ xr, const float* __restrict__ xi,
                  float* __restrict__ out) {
    __shared__ float sw[2*9*CC];
    __shared__ float sb[CC];
    for (int i = threadIdx.x; i < 2*9*CC; i += 256) sw[i] = g_w0[i];
    if (threadIdx.x < CC) sb[threadIdx.x] = g_b0[threadIdx.x];
    __syncthreads();

    int pix = blockIdx.x * 256 + threadIdx.x;
    if (pix >= BB*HWW) return;
    int b = pix / HWW;
    int p = pix - b*HWW;
    int y = p / WW, x = p - y*WW;

    const float* x0 = xr + b*HWW;
    const float* x1 = xi + b*HWW;
    float in[18];
    #pragma unroll
    for (int dy = 0; dy < 3; dy++) {
        #pragma unroll
        for (int dx = 0; dx < 3; dx++) {
            int yy = y + dy - 1, xx = x + dx - 1;
            bool ok = (yy >= 0) && (yy < HH) && (xx >= 0) && (xx < WW);
            in[dy*3 + dx]     = ok ? x0[yy*WW + xx] : 0.0f;
            in[9 + dy*3 + dx] = ok ? x1[yy*WW + xx] : 0.0f;
        }
    }

    for (int ci = 0; ci < NCH; ci++) {
        uint32_t u[8];
        #pragma unroll
        for (int j2 = 0; j2 < 8; j2++) {
            float a2[2];
            #pragma unroll
            for (int s = 0; s < 2; s++) {
                int cout = ci*CHUNK + 2*j2 + s;
                float acc = sb[cout];
                #pragma unroll
                for (int t = 0; t < 18; t++)
                    acc = fmaf(in[t], sw[t*CC + cout], acc);
                int f = cout % FF, c2 = cout / FF;
                out[((b*FF + f)*HWW + p)*2 + c2] = acc;
                a2[s] = sigma_f(acc);
            }
            __half2 hh = __floats2half2_rn(a2[0], a2[1]);
            u[j2] = *reinterpret_cast<uint32_t*>(&hh);
        }
        uint4* dst = reinterpret_cast<uint4*>(
            g_sig0 + ((size_t)(b*NCH + ci)*HWW + p)*CHUNK);
        dst[0] = make_uint4(u[0], u[1], u[2], u[3]);
        dst[1] = make_uint4(u[4], u[5], u[6], u[7]);
    }
}

// ---------------------------------------------------------------------------
// Layers 1,2: persistent-weight fp16 m16n8k16 implicit GEMM (R14 champion)
// + fused border correction: wrapped columns (x=0/x=319) are fixed in the
// epilogue by subtracting the exact leaked-tap contribution (fp32), computed
// from gmem acts + smem-resident weights. NO fixup kernels.
// ---------------------------------------------------------------------------
template<int LAYER>
__global__ __launch_bounds__(256, 1)
void convT_kernel(float* __restrict__ out) {
    extern __shared__ __align__(256) char smem_raw[];
    uint32_t sb_base = smem_u32(smem_raw);
    uint32_t sa_base[2] = { sb_base + SA_OFF, sb_base + SA_OFF + ABUF_BYTES };
    __half* s_sig  = reinterpret_cast<__half*>(smem_raw + SSIG_OFF);
    __half* s_fact = reinterpret_cast<__half*>(smem_raw + FIX_OFF);        // [2][3][96]
    float*  s_corr = reinterpret_cast<float*>(smem_raw + FIX_OFF + 1152);  // [2][96]

    const __half* __restrict__ sig_in = (LAYER == 1) ? g_sig0 : g_sig1;
    const __half* __restrict__ wg     = (LAYER == 1) ? g_w1 : g_w2;
    const float*  __restrict__ bg     = (LAYER == 1) ? g_b1 : g_b2;

    int tid  = threadIdx.x;
    int warp = tid >> 5, lane = tid & 31;
    int m0 = (warp >> 1) * 32;
    int n0 = (warp & 1) * 24;
    int gid = lane >> 2, qid = lane & 3;
    int arow = lane & 15;
    uint32_t akoff = (uint32_t)(lane >> 4) * 16;

    // stage ALL weights once (swizzle pre-baked -> flat memcpy)
    {
        const uint4* srcw = reinterpret_cast<const uint4*>(wg);
        uint4* dstw = reinterpret_cast<uint4*>(smem_raw);
        for (int i = tid; i < SB_BYTES/16; i += 256) dstw[i] = srcw[i];
    }

    // hoisted biases for this warp's n-tile
    float brl[3][2], bil[3][2];
    #pragma unroll
    for (int nt = 0; nt < 3; nt++) {
        int n = n0 + nt*8 + 2*qid;
        brl[nt][0] = __ldg(bg + n);      brl[nt][1] = __ldg(bg + n + 1);
        bil[nt][0] = __ldg(bg + n + 48); bil[nt][1] = __ldg(bg + n + 49);
    }
    __syncthreads();

    for (int job = blockIdx.x; job < NJOBS; job += gridDim.x) {
        int b     = job / NSTRIP;
        int strip = job - b*NSTRIP;
        int base  = strip * STRIP;
        int bx    = base % WW;          // in {0,128,256,64,192}
        const __half* plane0 = sig_in + (size_t)b*NCH*HWW*CHUNK;

        float acc[2][6][4];
        #pragma unroll
        for (int h = 0; h < 2; h++)
            #pragma unroll
            for (int nt = 0; nt < 6; nt++)
                #pragma unroll
                for (int r = 0; r < 4; r++) acc[h][nt][r] = 0.0f;

        // prefetch chunk 0 (flat bounds only — wrapped halos intentionally kept)
        {
            const __half* pc = plane0;
            for (int i = tid; i < 2*390; i += 256) {
                int blk = i >> 1, hi = i & 1;
                int dyr = blk / 130, px = blk - dyr*130;
                int fl  = base + (dyr - 1)*WW + px - 1;
                bool ok = (fl >= 0) && (fl < HWW);
                cp16(sa_base[0] + swz((uint32_t)(blk*32 + hi*16)),
                     pc + ((size_t)(ok ? fl : 0))*CHUNK + hi*8, ok);
            }
        }
        CP_COMMIT();

        for (int ci = 0; ci < NCH; ci++) {
            if (ci + 1 < NCH) {
                const __half* pc = plane0 + (size_t)(ci+1)*HWW*CHUNK;
                uint32_t ab = sa_base[(ci+1) & 1];
                for (int i = tid; i < 2*390; i += 256) {
                    int blk = i >> 1, hi = i & 1;
                    int dyr = blk / 130, px = blk - dyr*130;
                    int fl  = base + (dyr - 1)*WW + px - 1;
                    bool ok = (fl >= 0) && (fl < HWW);
                    cp16(ab + swz((uint32_t)(blk*32 + hi*16)),
                         pc + ((size_t)(ok ? fl : 0))*CHUNK + hi*8, ok);
                }
                CP_COMMIT();
                CP_WAIT1();
            } else {
                CP_WAIT0();
            }
            __syncthreads();

            uint32_t sa = sa_base[ci & 1];
            uint32_t cioff = (uint32_t)ci * (9*CC*32);
            #pragma unroll
            for (int tap = 0; tap < 9; tap++) {
                int dy = tap / 3, dx = tap - dy*3;
                uint32_t boff = cioff + (uint32_t)tap * (CC*32);
                uint32_t bf[6][2];
                #pragma unroll
                for (int nt = 0; nt < 6; nt++) {
                    int nrow = ((nt < 3) ? (n0 + nt*8) : (48 + n0 + (nt-3)*8)) + gid;
                    uint32_t o = boff + (uint32_t)nrow*32 + (uint32_t)qid*4;
                    bf[nt][0] = lds32(sb_base + swz(o));
                    bf[nt][1] = lds32(sb_base + swz(o + 16));
                }
                #pragma unroll
                for (int h = 0; h < 2; h++) {
                    int p = dy*130 + dx + m0 + h*16 + arow;
                    uint32_t a[4];
                    ldmA(a, sa + swz((uint32_t)p*32 + akoff));
                    #pragma unroll
                    for (int nt = 0; nt < 6; nt++)
                        mma_f16(acc[h][nt], a, bf[nt]);
                }
            }
            __syncthreads();
        }

        // --- border correction: subtract leaked-tap contributions (<=2 cols) ---
        int nfix = 0; int fm[2], fml[2], fldx[2];
        if (bx == 0)        { nfix = 1; fm[0]=0;   fml[0]=-1;  fldx[0]=0; }
        else if (bx == 192) { nfix = 1; fm[0]=127; fml[0]=128; fldx[0]=2; }
        else if (bx == 256) { nfix = 2; fm[0]=63;  fml[0]=64;  fldx[0]=2;
                              fm[1]=64; fml[1]=63; fldx[1]=0; }
        if (nfix) {
            // stage leaked acts [col][dy][c96] from gmem (same flat-bounds guard)
            for (int i = tid; i < 72; i += 256) {
                int col = i / 36, r = i % 36;
                int dyr = r / 12, j = r % 12;
                int ci = j >> 1, hi = j & 1;
                uint4 v = make_uint4(0u, 0u, 0u, 0u);
                if (col < nfix) {
                    int f = base + fml[col] + (dyr - 1)*WW;
                    if (f >= 0 && f < HWW)
                        v = *reinterpret_cast<const uint4*>(
                            sig_in + ((size_t)(b*NCH + ci)*HWW + f)*CHUNK + hi*8);
                }
                *reinterpret_cast<uint4*>(s_fact + col*288 + dyr*96 + ci*16 + hi*8) = v;
            }
            __syncthreads();
            if (tid < 192) {
                int col = tid / 96, cout = tid - (tid / 96)*96;
                float corr = 0.0f;
                if (col < nfix) {
                    int dx = fldx[col];
                    for (int ci = 0; ci < NCH; ci++)
                        #pragma unroll
                        for (int dyr = 0; dyr < 3; dyr++) {
                            uint32_t hb = (uint32_t)(((ci*9 + dyr*3 + dx)*CC + cout)*CHUNK);
                            const __half* w0p = reinterpret_cast<const __half*>(
                                smem_raw + swz(2*hb));
                            const __half* w1p = reinterpret_cast<const __half*>(
                                smem_raw + swz(2*hb + 16));
                            const __half* ap = s_fact + col*288 + dyr*96 + ci*16;
                            #pragma unroll
                            for (int k = 0; k < 8; k++)
                                corr = fmaf(__half2float(w0p[k]),
                                            __half2float(ap[k]), corr);
                            #pragma unroll
                            for (int k = 0; k < 8; k++)
                                corr = fmaf(__half2float(w1p[k]),
                                            __half2float(ap[8 + k]), corr);
                        }
                }
                s_corr[tid] = corr;
            }
            __syncthreads();
            #pragma unroll
            for (int col = 0; col < 2; col++) {
                if (col >= nfix) break;
                int fmc = fm[col];
                #pragma unroll
                for (int h = 0; h < 2; h++) {
                    int mm = m0 + h*16 + gid;
                    #pragma unroll
                    for (int nt = 0; nt < 6; nt++) {
                        int na = ((nt < 3) ? (n0 + nt*8) : (48 + n0 + (nt-3)*8)) + 2*qid;
                        if (mm == fmc) {
                            acc[h][nt][0] -= s_corr[col*96 + na];
                            acc[h][nt][1] -= s_corr[col*96 + na + 1];
                        }
                        if (mm + 8 == fmc) {
                            acc[h][nt][2] -= s_corr[col*96 + na];
                            acc[h][nt][3] -= s_corr[col*96 + na + 1];
                        }
                    }
                }
            }
        }

        // --- epilogue: direct float2 stores from fragments ---
        float2* ob = reinterpret_cast<float2*>(out)
                   + (size_t)(LAYER*BB + b)*FF*HWW + base;
        #pragma unroll
        for (int h = 0; h < 2; h++) {
            int m = m0 + h*16 + gid;
            #pragma unroll
            for (int nt = 0; nt < 3; nt++) {
                int n = n0 + nt*8 + 2*qid;
                float re0 = acc[h][nt][0] + brl[nt][0], re1 = acc[h][nt][1] + brl[nt][1];
                float re2 = acc[h][nt][2] + brl[nt][0], re3 = acc[h][nt][3] + brl[nt][1];
                float im0 = acc[h][nt+3][0] + bil[nt][0], im1 = acc[h][nt+3][1] + bil[nt][1];
                float im2 = acc[h][nt+3][2] + bil[nt][0], im3 = acc[h][nt+3][3] + bil[nt][1];
                ob[(size_t)n*HWW + m]         = make_float2(re0, im0);
                ob[(size_t)(n+1)*HWW + m]     = make_float2(re1, im1);
                ob[(size_t)n*HWW + m + 8]     = make_float2(re2, im2);
                ob[(size_t)(n+1)*HWW + m + 8] = make_float2(re3, im3);
                if (LAYER == 1) {
                    __half2* sg;
                    sg = reinterpret_cast<__half2*>(s_sig + m*CC + n);
                    *sg = __floats2half2_rn(sigma_f(re0), sigma_f(re1));
                    sg = reinterpret_cast<__half2*>(s_sig + m*CC + n + 48);
                    *sg = __floats2half2_rn(sigma_f(im0), sigma_f(im1));
                    sg = reinterpret_cast<__half2*>(s_sig + (m+8)*CC + n);
                    *sg = __floats2half2_rn(sigma_f(re2), sigma_f(re3));
                    sg = reinterpret_cast<__half2*>(s_sig + (m+8)*CC + n + 48);
                    *sg = __floats2half2_rn(sigma_f(im2), sigma_f(im3));
                }
            }
        }
        if (LAYER == 1) {
            __syncthreads();   // s_sig complete across warps
            for (int i = tid; i < NCH*STRIP; i += 256) {
                int ci = i >> 7;
                int px = i & (STRIP-1);
                const uint4* srcv = reinterpret_cast<const uint4*>(
                    s_sig + px*CC + ci*CHUNK);
                uint4* dst = reinterpret_cast<uint4*>(
                    g_sig1 + ((size_t)(b*NCH + ci)*HWW + base + px)*CHUNK);
                dst[0] = srcv[0];
                dst[1] = srcv[1];
            }
            __syncthreads();   // s_sig aliases A buffers: done before next prefetch
        }
    }
}

extern "C" void kernel_launch(void* const* d_in, const int* in_sizes, int n_in,
                              void* d_out, int out_size) {
    const float* x_real = (const float*)d_in[0];
    const float* x_imag = (const float*)d_in[1];
    const float* w0r = (const float*)d_in[2];
    const float* w0i = (const float*)d_in[3];
    const float* b0r = (const float*)d_in[4];
    const float* b0i = (const float*)d_in[5];
    const float* w1r = (const float*)d_in[6];
    const float* w1i = (const float*)d_in[7];
    const float* b1r = (const float*)d_in[8];
    const float* b1i = (const float*)d_in[9];
    const float* w2r = (const float*)d_in[10];
    const float* w2i = (const float*)d_in[11];
    const float* b2r = (const float*)d_in[12];
    const float* b2i = (const float*)d_in[13];
    float* out = (float*)d_out;

    static bool attr_set = false;
    if (!attr_set) {
        cudaFuncSetAttribute(convT_kernel<1>, cudaFuncAttributeMaxDynamicSharedMemorySize, SMEM_BYTES);
        cudaFuncSetAttribute(convT_kernel<2>, cudaFuncAttributeMaxDynamicSharedMemorySize, SMEM_BYTES);
        attr_set = true;
    }

    repack_all<<<(REPACK_TOTAL + 255)/256, 256>>>(
        w0r, w0i, b0r, b0i, w1r, w1i, b1r, b1i, w2r, w2i, b2r, b2i);

    conv0_kernel<<<(BB*HWW + 255)/256, 256>>>(x_real, x_imag, out);

    convT_kernel<1><<<NCTAS, 256, SMEM_BYTES>>>(out);
    convT_kernel<2><<<NCTAS, 256, SMEM_BYTES>>>(out);
}